// round 9
// baseline (speedup 1.0000x reference)
#include <cuda_runtime.h>
#include <math.h>
#include <stdint.h>

// ---------------- Problem dims ----------------
#define B_  2
#define T_  2048
#define D_  1024
#define H_  16
#define HS_ 64
#define BT_ (B_*T_)      // 4096
#define BH_ (B_*H_)      // 32
#define EPS_ 1e-5f

// ---------------- Scratch (static device memory; no allocations) ----------------
__device__ __align__(16) float g_xln [BT_*D_];
__device__ __align__(16) float g_q   [BT_*D_];     // [B,T,H,HS]
__device__ __align__(16) float g_k   [BT_*D_];
__device__ __align__(16) float g_v   [BT_*D_];
__device__ __align__(16) float g_res1[BT_*D_];
__device__ __align__(16) float g_ffh [(size_t)BT_*4*D_];

// ---------------- Helpers ----------------
__device__ __forceinline__ float f2tf(float f) {
    uint32_t r;
    asm("cvt.rna.tf32.f32 %0, %1;" : "=r"(r) : "f"(f));
    return __uint_as_float(r);
}
__device__ __forceinline__ void mma_tf32(float& c0, float& c1, float& c2, float& c3,
                                         float a0, float a1, float a2, float a3,
                                         float b0, float b1)
{
    uint32_t ua0 = __float_as_uint(a0), ua1 = __float_as_uint(a1);
    uint32_t ua2 = __float_as_uint(a2), ua3 = __float_as_uint(a3);
    uint32_t ub0 = __float_as_uint(b0), ub1 = __float_as_uint(b1);
    asm volatile("mma.sync.aligned.m16n8k8.row.col.f32.tf32.tf32.f32 "
                 "{%0,%1,%2,%3}, {%4,%5,%6,%7}, {%8,%9}, {%0,%1,%2,%3};"
                 : "+f"(c0), "+f"(c1), "+f"(c2), "+f"(c3)
                 : "r"(ua0), "r"(ua1), "r"(ua2), "r"(ua3), "r"(ub0), "r"(ub1));
}
// pack two fp32 -> f16x2 {lo, hi}
__device__ __forceinline__ uint32_t pk16(float lo, float hi) {
    uint32_t d;
    asm("cvt.rn.f16x2.f32 %0, %1, %2;" : "=r"(d) : "f"(hi), "f"(lo));
    return d;
}
__device__ __forceinline__ void mma_f16(float& c0, float& c1, float& c2, float& c3,
                                        uint32_t a0, uint32_t a1, uint32_t a2, uint32_t a3,
                                        uint32_t b0, uint32_t b1)
{
    asm volatile("mma.sync.aligned.m16n8k16.row.col.f32.f16.f16.f32 "
                 "{%0,%1,%2,%3}, {%4,%5,%6,%7}, {%8,%9}, {%0,%1,%2,%3};"
                 : "+f"(c0), "+f"(c1), "+f"(c2), "+f"(c3)
                 : "r"(a0), "r"(a1), "r"(a2), "r"(a3), "r"(b0), "r"(b1));
}
__device__ __forceinline__ void cp16(float* s, const float* g) {
    uint32_t sa = (uint32_t)__cvta_generic_to_shared(s);
    asm volatile("cp.async.cg.shared.global [%0], [%1], 16;" :: "r"(sa), "l"(g));
}
__device__ __forceinline__ void cp_commit() { asm volatile("cp.async.commit_group;" ::: "memory"); }
template<int N>
__device__ __forceinline__ void cp_wait() { asm volatile("cp.async.wait_group %0;" :: "n"(N) : "memory"); }

// ---------------- LayerNorm (plain fp32 output; GEMMs round on read) ----------------
__global__ __launch_bounds__(256) void ln_kernel(const float* __restrict__ x,
                                                 const float* __restrict__ gam,
                                                 const float* __restrict__ bet,
                                                 float* __restrict__ y)
{
    const int row = blockIdx.x;
    const int tid = threadIdx.x;
    const float4 v = *(const float4*)(x + (size_t)row*D_ + tid*4);
    float s  = v.x + v.y + v.z + v.w;
    float s2 = v.x*v.x + v.y*v.y + v.z*v.z + v.w*v.w;
    __shared__ float shs[8], shs2[8], stat[2];
    #pragma unroll
    for (int o = 16; o; o >>= 1) {
        s  += __shfl_xor_sync(0xffffffffu, s,  o);
        s2 += __shfl_xor_sync(0xffffffffu, s2, o);
    }
    if ((tid & 31) == 0) { shs[tid >> 5] = s; shs2[tid >> 5] = s2; }
    __syncthreads();
    if (tid == 0) {
        float ts = 0.f, ts2 = 0.f;
        #pragma unroll
        for (int w = 0; w < 8; ++w) { ts += shs[w]; ts2 += shs2[w]; }
        float mean = ts * (1.0f / D_);
        float var  = ts2 * (1.0f / D_) - mean * mean;
        stat[0] = mean; stat[1] = rsqrtf(var + EPS_);
    }
    __syncthreads();
    const float mean = stat[0], rstd = stat[1];
    const float4 g4 = *(const float4*)(gam + tid*4);
    const float4 b4 = *(const float4*)(bet + tid*4);
    float4 o;
    o.x = (v.x - mean) * rstd * g4.x + b4.x;
    o.y = (v.y - mean) * rstd * g4.y + b4.y;
    o.z = (v.z - mean) * rstd * g4.z + b4.z;
    o.w = (v.w - mean) * rstd * g4.w + b4.w;
    *(float4*)(y + (size_t)row*D_ + tid*4) = o;
}

// ---------------- cp.async fp16 GEMM: 128x128 tile, BK=16, m16n8k16 ----------------
// MODE 0: QKV (blockIdx.z selects Wq/Wk/Wv and q/k/v; MAPB weight layout, no bias)
// MODE 1: FFN1 (bias + relu)
// MODE 2: FFN2 (bias + residual)
#define ASTR 20
#define BSTR 132

template<int MODE>
__global__ __launch_bounds__(256) void tgemm_kernel(
    const float* __restrict__ A,
    const float* __restrict__ B0, const float* __restrict__ B1, const float* __restrict__ B2,
    const float* __restrict__ bias, const float* __restrict__ res,
    float* __restrict__ C0, float* __restrict__ C1, float* __restrict__ C2,
    int M, int N, int K)
{
    __shared__ __align__(16) float As[2][128][ASTR];
    __shared__ __align__(16) float Bs[2][16][BSTR];

    const float* Bm;
    float* C;
    if (MODE == 0) {
        Bm = (blockIdx.z == 0) ? B0 : (blockIdx.z == 1 ? B1 : B2);
        C  = (blockIdx.z == 0) ? C0 : (blockIdx.z == 1 ? C1 : C2);
    } else {
        Bm = B0;
        C  = C0;
    }

    const int tid  = threadIdx.x;
    const int m0 = blockIdx.y * 128, n0 = blockIdx.x * 128;
    const int warp = tid >> 5, lane = tid & 31;
    const int gid = lane >> 2, tig = lane & 3;
    const int wm = (warp >> 2) * 64;   // 0,64
    const int wn = (warp & 3) * 32;    // 0,32,64,96

    // per-thread load coords (2 float4 each for A and B per 16-k tile)
    const int lar0 = (tid      ) >> 2, lac0 = ((tid      ) & 3) * 4;
    const int lar1 = (tid + 256) >> 2, lac1 = ((tid + 256) & 3) * 4;
    const int lbk0 = (tid      ) >> 5, lbn0 = ((tid      ) & 31) * 4;
    const int lbk1 = (tid + 256) >> 5, lbn1 = ((tid + 256) & 31) * 4;

    float acc[4][4][4];
    #pragma unroll
    for (int t = 0; t < 4; ++t)
        #pragma unroll
        for (int u = 0; u < 4; ++u)
            #pragma unroll
            for (int c = 0; c < 4; ++c) acc[t][u][c] = 0.f;

    const int ntiles = K >> 4;

    // prologue: stage tile 0 into buffer 0
    {
        cp16(&As[0][lar0][lac0], A + (size_t)(m0 + lar0) * K + lac0);
        cp16(&As[0][lar1][lac1], A + (size_t)(m0 + lar1) * K + lac1);
        if (MODE == 0) {
            int col0 = n0 + lbn0, col1 = n0 + lbn1;
            cp16(&Bs[0][lbk0][lbn0], Bm + ((size_t)(col0 >> 6) * K + lbk0) * HS_ + (col0 & 63));
            cp16(&Bs[0][lbk1][lbn1], Bm + ((size_t)(col1 >> 6) * K + lbk1) * HS_ + (col1 & 63));
        } else {
            cp16(&Bs[0][lbk0][lbn0], Bm + (size_t)lbk0 * N + n0 + lbn0);
            cp16(&Bs[0][lbk1][lbn1], Bm + (size_t)lbk1 * N + n0 + lbn1);
        }
        cp_commit();
    }

    for (int t = 0; t < ntiles; ++t) {
        const int cur = t & 1;
        if (t + 1 < ntiles) {
            const int k0 = (t + 1) << 4;
            const int nb = cur ^ 1;
            cp16(&As[nb][lar0][lac0], A + (size_t)(m0 + lar0) * K + k0 + lac0);
            cp16(&As[nb][lar1][lac1], A + (size_t)(m0 + lar1) * K + k0 + lac1);
            if (MODE == 0) {
                int col0 = n0 + lbn0, col1 = n0 + lbn1;
                cp16(&Bs[nb][lbk0][lbn0], Bm + ((size_t)(col0 >> 6) * K + k0 + lbk0) * HS_ + (col0 & 63));
                cp16(&Bs[nb][lbk1][lbn1], Bm + ((size_t)(col1 >> 6) * K + k0 + lbk1) * HS_ + (col1 & 63));
            } else {
                cp16(&Bs[nb][lbk0][lbn0], Bm + (size_t)(k0 + lbk0) * N + n0 + lbn0);
                cp16(&Bs[nb][lbk1][lbn1], Bm + (size_t)(k0 + lbk1) * N + n0 + lbn1);
            }
            cp_commit();
            cp_wait<1>();
        } else {
            cp_wait<0>();
        }
        __syncthreads();

        // ---- one m16n8k16 step covers the whole BK=16 tile ----
        uint32_t bf[4][2];
        #pragma unroll
        for (int u = 0; u < 4; ++u) {
            const int col = wn + u*8 + gid;
            bf[u][0] = pk16(Bs[cur][tig*2    ][col], Bs[cur][tig*2 + 1][col]);
            bf[u][1] = pk16(Bs[cur][tig*2 + 8][col], Bs[cur][tig*2 + 9][col]);
        }
        #pragma unroll
        for (int tt = 0; tt < 4; ++tt) {
            const int rr = wm + tt * 16;
            const float2 p0 = *(const float2*)(&As[cur][rr + gid    ][tig*2]);
            const float2 p1 = *(const float2*)(&As[cur][rr + gid + 8][tig*2]);
            const float2 p2 = *(const float2*)(&As[cur][rr + gid    ][tig*2 + 8]);
            const float2 p3 = *(const float2*)(&As[cur][rr + gid + 8][tig*2 + 8]);
            const uint32_t a0 = pk16(p0.x, p0.y);
            const uint32_t a1 = pk16(p1.x, p1.y);
            const uint32_t a2 = pk16(p2.x, p2.y);
            const uint32_t a3 = pk16(p3.x, p3.y);
            #pragma unroll
            for (int u = 0; u < 4; ++u)
                mma_f16(acc[tt][u][0], acc[tt][u][1], acc[tt][u][2], acc[tt][u][3],
                        a0, a1, a2, a3, bf[u][0], bf[u][1]);
        }
        __syncthreads();
    }

    // ---- epilogue ----
    #pragma unroll
    for (int t = 0; t < 4; ++t) {
        #pragma unroll
        for (int u = 0; u < 4; ++u) {
            const int m = m0 + wm + t*16 + gid;
            const int n = n0 + wn + u*8 + tig*2;
            float v0 = acc[t][u][0], v1 = acc[t][u][1];
            float v2 = acc[t][u][2], v3 = acc[t][u][3];
            if (MODE >= 1) {
                float b0 = bias[n], b1 = bias[n+1];
                v0 += b0; v1 += b1; v2 += b0; v3 += b1;
            }
            if (MODE == 1) {
                v0 = fmaxf(v0, 0.f); v1 = fmaxf(v1, 0.f);
                v2 = fmaxf(v2, 0.f); v3 = fmaxf(v3, 0.f);
            }
            if (MODE == 2) {
                const float2 r0 = *(const float2*)(res + (size_t)m * N + n);
                const float2 r1 = *(const float2*)(res + (size_t)(m+8) * N + n);
                v0 += r0.x; v1 += r0.y; v2 += r1.x; v3 += r1.y;
            }
            *(float2*)(C + (size_t)m * N + n)       = make_float2(v0, v1);
            *(float2*)(C + (size_t)(m+8) * N + n)   = make_float2(v2, v3);
        }
    }
}

// ---------------- Flash attention (R7/R8 exact): static smem, 128 thr, 64-row CTA ----------------
__global__ __launch_bounds__(128) void flash_kernel(const float* __restrict__ embds,
                                                    float* __restrict__ out)
{
    __shared__ float Qs[64][68];
    __shared__ float Ks[32][68];
    __shared__ float Vs[32][72];
    __shared__ float Ps[64][36];

    const int it = gridDim.x - 1 - blockIdx.x;   // heavy tiles first
    const int bh = blockIdx.y;
    const int b = bh >> 4, h = bh & 15;
    const int tid = threadIdx.x, warp = tid >> 5, lane = tid & 31;
    const int gid = lane >> 2, tig = lane & 3;
    const int i0 = it * 64;
    const int wr = i0 + warp * 16;

    #pragma unroll
    for (int l = 0; l < 8; ++l) {
        int idx = l * 128 + tid;
        int r = idx >> 4, e4 = (idx & 15) * 4;
        float4 qv = *(const float4*)(g_q + (((size_t)(b*T_ + i0 + r))*H_ + h)*HS_ + e4);
        qv.x = f2tf(qv.x); qv.y = f2tf(qv.y); qv.z = f2tf(qv.z); qv.w = f2tf(qv.w);
        *(float4*)(&Qs[r][e4]) = qv;
    }

    float oacc[8][4];
    #pragma unroll
    for (int u = 0; u < 8; ++u)
        #pragma unroll
        for (int c = 0; c < 4; ++c) oacc[u][c] = 0.f;
    float mrow[2] = {-1e30f, -1e30f};
    float lrow[2] = {0.f, 0.f};

    const int njc = 2*it + 2;
    for (int jc = 0; jc < njc; ++jc) {
        const int j0 = jc * 32;
        __syncthreads();
        #pragma unroll
        for (int l = 0; l < 4; ++l) {
            int idx = l * 128 + tid;
            int r = idx >> 4, e4 = (idx & 15) * 4;
            const size_t grow = (((size_t)(b*T_ + j0 + r))*H_ + h)*HS_ + e4;
            float4 kv = *(const float4*)(g_k + grow);
            kv.x = f2tf(kv.x); kv.y = f2tf(kv.y); kv.z = f2tf(kv.z); kv.w = f2tf(kv.w);
            *(float4*)(&Ks[r][e4]) = kv;
            float4 vv = *(const float4*)(g_v + grow);
            vv.x = f2tf(vv.x); vv.y = f2tf(vv.y); vv.z = f2tf(vv.z); vv.w = f2tf(vv.w);
            *(float4*)(&Vs[r][e4]) = vv;
        }
        __syncthreads();

        if (j0 <= wr + 15) {
            float sacc[4][4];
            #pragma unroll
            for (int u = 0; u < 4; ++u)
                #pragma unroll
                for (int c = 0; c < 4; ++c) sacc[u][c] = 0.f;
            #pragma unroll
            for (int kc = 0; kc < 8; ++kc) {
                const int kb = kc * 8;
                float a0 = Qs[warp*16 + gid    ][kb + tig];
                float a1 = Qs[warp*16 + gid + 8][kb + tig];
                float a2 = Qs[warp*16 + gid    ][kb + tig + 4];
                float a3 = Qs[warp*16 + gid + 8][kb + tig + 4];
                #pragma unroll
                for (int u = 0; u < 4; ++u) {
                    float b0 = Ks[u*8 + gid][kb + tig];
                    float b1 = Ks[u*8 + gid][kb + tig + 4];
                    mma_tf32(sacc[u][0], sacc[u][1], sacc[u][2], sacc[u][3],
                             a0, a1, a2, a3, b0, b1);
                }
            }

            const bool maskneed = (j0 + 31 > wr);
            #pragma unroll
            for (int rh = 0; rh < 2; ++rh) {
                const int row = wr + gid + rh*8;
                float tmax = -1e30f;
                #pragma unroll
                for (int u = 0; u < 4; ++u) {
                    float x0 = sacc[u][rh*2    ] * 0.03125f;
                    float x1 = sacc[u][rh*2 + 1] * 0.03125f;
                    if (maskneed) {
                        const int c = j0 + u*8 + tig*2;
                        if (c     > row) x0 = -1e30f;
                        if (c + 1 > row) x1 = -1e30f;
                    }
                    sacc[u][rh*2    ] = x0;
                    sacc[u][rh*2 + 1] = x1;
                    tmax = fmaxf(tmax, fmaxf(x0, x1));
                }
                tmax = fmaxf(tmax, __shfl_xor_sync(0xffffffffu, tmax, 1));
                tmax = fmaxf(tmax, __shfl_xor_sync(0xffffffffu, tmax, 2));
                const float mnew = fmaxf(mrow[rh], tmax);
                const float corr = __expf(mrow[rh] - mnew);
                float rsum = 0.f;
                #pragma unroll
                for (int u = 0; u < 4; ++u) {
                    float p0 = __expf(sacc[u][rh*2    ] - mnew);
                    float p1 = __expf(sacc[u][rh*2 + 1] - mnew);
                    rsum += p0 + p1;
                    *(float2*)(&Ps[warp*16 + gid + rh*8][u*8 + tig*2]) =
                        make_float2(f2tf(p0), f2tf(p1));
                }
                #pragma unroll
                for (int uu = 0; uu < 8; ++uu) {
                    oacc[uu][rh*2    ] *= corr;
                    oacc[uu][rh*2 + 1] *= corr;
                }
                rsum += __shfl_xor_sync(0xffffffffu, rsum, 1);
                rsum += __shfl_xor_sync(0xffffffffu, rsum, 2);
                lrow[rh] = lrow[rh] * corr + rsum;
                mrow[rh] = mnew;
            }
            __syncwarp();

            #pragma unroll
            for (int kc = 0; kc < 4; ++kc) {
                const int kb = kc * 8;
                float a0 = Ps[warp*16 + gid    ][kb + tig];
                float a1 = Ps[warp*16 + gid + 8][kb + tig];
                float a2 = Ps[warp*16 + gid    ][kb + tig + 4];
                float a3 = Ps[warp*16 + gid + 8][kb + tig + 4];
                #pragma unroll
                for (int u = 0; u < 8; ++u) {
                    float b0 = Vs[kb + tig    ][u*8 + gid];
                    float b1 = Vs[kb + tig + 4][u*8 + gid];
                    mma_tf32(oacc[u][0], oacc[u][1], oacc[u][2], oacc[u][3],
                             a0, a1, a2, a3, b0, b1);
                }
            }
        }
    }

    #pragma unroll
    for (int rh = 0; rh < 2; ++rh) {
        const int t = wr + gid + rh*8;
        const float inv = 1.0f / lrow[rh];
        #pragma unroll
        for (int u = 0; u < 8; ++u) {
            const int d = h * HS_ + u*8 + tig*2;
            const size_t o = ((size_t)(b*T_ + t))*D_ + d;
            const float2 e = *(const float2*)(embds + o);
            *(float2*)(out + o) = make_float2(e.x + oacc[u][rh*2    ]*inv,
                                              e.y + oacc[u][rh*2 + 1]*inv);
        }
    }
}

// ---------------- Launcher ----------------
extern "C" void kernel_launch(void* const* d_in, const int* in_sizes, int n_in,
                              void* d_out, int out_size)
{
    const float* embds = (const float*)d_in[0];
    const float* Wq    = (const float*)d_in[1];
    const float* Wk    = (const float*)d_in[2];
    const float* Wv    = (const float*)d_in[3];
    const float* ln1g  = (const float*)d_in[4];
    const float* ln1b  = (const float*)d_in[5];
    const float* ln2g  = (const float*)d_in[6];
    const float* ln2b  = (const float*)d_in[7];
    const float* W1    = (const float*)d_in[8];
    const float* b1    = (const float*)d_in[9];
    const float* W2    = (const float*)d_in[10];
    const float* b2    = (const float*)d_in[11];
    float* out = (float*)d_out;

    float *xln, *q, *k, *v, *res1, *ffh;
    cudaGetSymbolAddress((void**)&xln,  g_xln);
    cudaGetSymbolAddress((void**)&q,    g_q);
    cudaGetSymbolAddress((void**)&k,    g_k);
    cudaGetSymbolAddress((void**)&v,    g_v);
    cudaGetSymbolAddress((void**)&res1, g_res1);
    cudaGetSymbolAddress((void**)&ffh,  g_ffh);

    // 1. LN1
    ln_kernel<<<BT_, 256>>>(embds, ln1g, ln1b, xln);

    // 2. Fused QKV via gridDim.z (block-uniform pointer select) -> q,k,v [B,T,H,HS]
    tgemm_kernel<0><<<dim3(D_/128, BT_/128, 3), 256>>>(
        xln, Wq, Wk, Wv, nullptr, nullptr, q, k, v, BT_, D_, D_);

    // 3. Flash attention + head-concat + residual -> res1
    flash_kernel<<<dim3(T_/64, BH_), 128>>>(embds, res1);

    // 4. LN2
    ln_kernel<<<BT_, 256>>>(res1, ln2g, ln2b, xln);

    // 5. FFN1: relu(y @ W1 + b1) -> ffh
    tgemm_kernel<1><<<dim3(4*D_/128, BT_/128), 256>>>(
        xln, W1, nullptr, nullptr, b1, nullptr, ffh, nullptr, nullptr, BT_, 4*D_, D_);

    // 6. FFN2: ffh @ W2 + b2 + res1 -> out
    tgemm_kernel<2><<<dim3(D_/128, BT_/128), 256>>>(
        ffh, W2, nullptr, nullptr, b2, res1, out, nullptr, nullptr, BT_, D_, 4*D_);
}

// round 11
// speedup vs baseline: 1.2955x; 1.2955x over previous
#include <cuda_runtime.h>
#include <cuda_fp16.h>
#include <math.h>
#include <stdint.h>

// ---------------- Problem dims ----------------
#define B_  2
#define T_  2048
#define D_  1024
#define H_  16
#define HS_ 64
#define BT_ (B_*T_)      // 4096
#define BH_ (B_*H_)      // 32
#define EPS_ 1e-5f

// ---------------- Scratch (static device memory; no allocations) ----------------
__device__ __align__(16) __half g_xh [BT_*D_];            // LN out, fp16 (GEMM A-side only)
__device__ __align__(16) __half g_fh [(size_t)BT_*4*D_];  // FFN1 out, fp16 (GEMM A-side only)
__device__ __align__(16) float  g_q  [BT_*D_];            // [B,T,H,HS]
__device__ __align__(16) float  g_k  [BT_*D_];
__device__ __align__(16) float  g_v  [BT_*D_];
__device__ __align__(16) float  g_res1[BT_*D_];

// ---------------- Helpers ----------------
__device__ __forceinline__ float f2tf(float f) {
    uint32_t r;
    asm("cvt.rna.tf32.f32 %0, %1;" : "=r"(r) : "f"(f));
    return __uint_as_float(r);
}
__device__ __forceinline__ void mma_tf32(float& c0, float& c1, float& c2, float& c3,
                                         float a0, float a1, float a2, float a3,
                                         float b0, float b1)
{
    uint32_t ua0 = __float_as_uint(a0), ua1 = __float_as_uint(a1);
    uint32_t ua2 = __float_as_uint(a2), ua3 = __float_as_uint(a3);
    uint32_t ub0 = __float_as_uint(b0), ub1 = __float_as_uint(b1);
    asm volatile("mma.sync.aligned.m16n8k8.row.col.f32.tf32.tf32.f32 "
                 "{%0,%1,%2,%3}, {%4,%5,%6,%7}, {%8,%9}, {%0,%1,%2,%3};"
                 : "+f"(c0), "+f"(c1), "+f"(c2), "+f"(c3)
                 : "r"(ua0), "r"(ua1), "r"(ua2), "r"(ua3), "r"(ub0), "r"(ub1));
}
__device__ __forceinline__ uint32_t pk16(float lo, float hi) {
    uint32_t d;
    asm("cvt.rn.f16x2.f32 %0, %1, %2;" : "=r"(d) : "f"(hi), "f"(lo));
    return d;
}
__device__ __forceinline__ void mma_f16(float& c0, float& c1, float& c2, float& c3,
                                        uint32_t a0, uint32_t a1, uint32_t a2, uint32_t a3,
                                        uint32_t b0, uint32_t b1)
{
    asm volatile("mma.sync.aligned.m16n8k16.row.col.f32.f16.f16.f32 "
                 "{%0,%1,%2,%3}, {%4,%5,%6,%7}, {%8,%9}, {%0,%1,%2,%3};"
                 : "+f"(c0), "+f"(c1), "+f"(c2), "+f"(c3)
                 : "r"(a0), "r"(a1), "r"(a2), "r"(a3), "r"(b0), "r"(b1));
}
__device__ __forceinline__ void cp16(void* s, const void* g) {
    uint32_t sa = (uint32_t)__cvta_generic_to_shared(s);
    asm volatile("cp.async.cg.shared.global [%0], [%1], 16;" :: "r"(sa), "l"(g));
}
__device__ __forceinline__ void cp_commit() { asm volatile("cp.async.commit_group;" ::: "memory"); }
template<int N>
__device__ __forceinline__ void cp_wait() { asm volatile("cp.async.wait_group %0;" :: "n"(N) : "memory"); }
__device__ __forceinline__ void ldsm4(uint32_t& a0, uint32_t& a1, uint32_t& a2, uint32_t& a3,
                                      uint32_t addr)
{
    asm volatile("ldmatrix.sync.aligned.m8n8.x4.shared.b16 {%0,%1,%2,%3}, [%4];"
                 : "=r"(a0), "=r"(a1), "=r"(a2), "=r"(a3) : "r"(addr));
}

// ---------------- LayerNorm (fp16 output: feeds GEMM A-sides only) ----------------
__global__ __launch_bounds__(256) void ln_kernel(const float* __restrict__ x,
                                                 const float* __restrict__ gam,
                                                 const float* __restrict__ bet,
                                                 __half* __restrict__ y)
{
    const int row = blockIdx.x;
    const int tid = threadIdx.x;
    const float4 v = *(const float4*)(x + (size_t)row*D_ + tid*4);
    float s  = v.x + v.y + v.z + v.w;
    float s2 = v.x*v.x + v.y*v.y + v.z*v.z + v.w*v.w;
    __shared__ float shs[8], shs2[8], stat[2];
    #pragma unroll
    for (int o = 16; o; o >>= 1) {
        s  += __shfl_xor_sync(0xffffffffu, s,  o);
        s2 += __shfl_xor_sync(0xffffffffu, s2, o);
    }
    if ((tid & 31) == 0) { shs[tid >> 5] = s; shs2[tid >> 5] = s2; }
    __syncthreads();
    if (tid == 0) {
        float ts = 0.f, ts2 = 0.f;
        #pragma unroll
        for (int w = 0; w < 8; ++w) { ts += shs[w]; ts2 += shs2[w]; }
        float mean = ts * (1.0f / D_);
        float var  = ts2 * (1.0f / D_) - mean * mean;
        stat[0] = mean; stat[1] = rsqrtf(var + EPS_);
    }
    __syncthreads();
    const float mean = stat[0], rstd = stat[1];
    const float4 g4 = *(const float4*)(gam + tid*4);
    const float4 b4 = *(const float4*)(bet + tid*4);
    __half2 ha = __floats2half2_rn((v.x - mean) * rstd * g4.x + b4.x,
                                   (v.y - mean) * rstd * g4.y + b4.y);
    __half2 hb = __floats2half2_rn((v.z - mean) * rstd * g4.z + b4.z,
                                   (v.w - mean) * rstd * g4.w + b4.w);
    __half2* yp = (__half2*)(y + (size_t)row*D_ + tid*4);
    yp[0] = ha; yp[1] = hb;
}

// ---------------- fp16-A GEMM: 128x128 tile, BK=16, m16n8k16, ldmatrix A ----------------
// A: fp16 global (pre-converted by producer). B: fp32 weights, packed to f16x2 at frag read.
// MODE 0: QKV (blockIdx.z selects W / output; MAPB layout, no bias)  -> fp32 out
// MODE 1: FFN1 (bias + relu)                                          -> fp16 out
// MODE 2: FFN2 (bias + residual)                                      -> fp32 out
#define ASTRH 24
#define BSTR  132

template<int MODE>
__global__ __launch_bounds__(256) void tgemm_kernel(
    const __half* __restrict__ A,
    const float* __restrict__ B0, const float* __restrict__ B1, const float* __restrict__ B2,
    const float* __restrict__ bias, const float* __restrict__ res,
    float* __restrict__ C0, float* __restrict__ C1, float* __restrict__ C2,
    int M, int N, int K)
{
    __shared__ __align__(16) __half As[2][128][ASTRH];
    __shared__ __align__(16) float  Bs[2][16][BSTR];

    const float* Bm;
    float* C;
    if (MODE == 0) {
        Bm = (blockIdx.z == 0) ? B0 : (blockIdx.z == 1 ? B1 : B2);
        C  = (blockIdx.z == 0) ? C0 : (blockIdx.z == 1 ? C1 : C2);
    } else {
        Bm = B0;
        C  = C0;
    }

    const int tid  = threadIdx.x;
    const int m0 = blockIdx.y * 128, n0 = blockIdx.x * 128;
    const int warp = tid >> 5, lane = tid & 31;
    const int gid = lane >> 2, tig = lane & 3;
    const int wm = (warp >> 2) * 64;   // 0,64
    const int wn = (warp & 3) * 32;    // 0,32,64,96

    // ldmatrix per-lane source coords within a 16x16 A tile
    const int ldrow = (lane & 7) + ((lane >> 3) & 1) * 8;
    const int ldcol = (lane >> 4) * 8;
    const uint32_t asBase = (uint32_t)__cvta_generic_to_shared(&As[0][0][0]);

    // A fill: 1 x 16B per thread per tile (128 rows x 16 halves)
    const int lar = tid >> 1;
    const int lacH = (tid & 1) * 8;
    // B fill: 2 x 16B per thread per tile (16 rows x 128 floats)
    const int lbk0 = (tid      ) >> 5, lbn0 = ((tid      ) & 31) * 4;
    const int lbk1 = (tid + 256) >> 5, lbn1 = ((tid + 256) & 31) * 4;

    const __half* Aread = A + (size_t)(m0 + lar) * K + lacH;

    float acc[4][4][4];
    #pragma unroll
    for (int t = 0; t < 4; ++t)
        #pragma unroll
        for (int u = 0; u < 4; ++u)
            #pragma unroll
            for (int c = 0; c < 4; ++c) acc[t][u][c] = 0.f;

    const int ntiles = K >> 4;

    // prologue: stage tile 0 into buffer 0
    {
        cp16(&As[0][lar][lacH], Aread);
        if (MODE == 0) {
            int col0 = n0 + lbn0, col1 = n0 + lbn1;
            cp16(&Bs[0][lbk0][lbn0], Bm + ((size_t)(col0 >> 6) * K + lbk0) * HS_ + (col0 & 63));
            cp16(&Bs[0][lbk1][lbn1], Bm + ((size_t)(col1 >> 6) * K + lbk1) * HS_ + (col1 & 63));
        } else {
            cp16(&Bs[0][lbk0][lbn0], Bm + (size_t)lbk0 * N + n0 + lbn0);
            cp16(&Bs[0][lbk1][lbn1], Bm + (size_t)lbk1 * N + n0 + lbn1);
        }
        cp_commit();
    }

    for (int t = 0; t < ntiles; ++t) {
        const int cur = t & 1;
        if (t + 1 < ntiles) {
            const int k0 = (t + 1) << 4;
            const int nb = cur ^ 1;
            cp16(&As[nb][lar][lacH], Aread + k0);
            if (MODE == 0) {
                int col0 = n0 + lbn0, col1 = n0 + lbn1;
                cp16(&Bs[nb][lbk0][lbn0], Bm + ((size_t)(col0 >> 6) * K + k0 + lbk0) * HS_ + (col0 & 63));
                cp16(&Bs[nb][lbk1][lbn1], Bm + ((size_t)(col1 >> 6) * K + k0 + lbk1) * HS_ + (col1 & 63));
            } else {
                cp16(&Bs[nb][lbk0][lbn0], Bm + (size_t)(k0 + lbk0) * N + n0 + lbn0);
                cp16(&Bs[nb][lbk1][lbn1], Bm + (size_t)(k0 + lbk1) * N + n0 + lbn1);
            }
            cp_commit();
            cp_wait<1>();
        } else {
            cp_wait<0>();
        }
        __syncthreads();

        // ---- B fragments: fp32 smem -> f16x2 (validated in R9) ----
        uint32_t bf[4][2];
        #pragma unroll
        for (int u = 0; u < 4; ++u) {
            const int col = wn + u*8 + gid;
            bf[u][0] = pk16(Bs[cur][tig*2    ][col], Bs[cur][tig*2 + 1][col]);
            bf[u][1] = pk16(Bs[cur][tig*2 + 8][col], Bs[cur][tig*2 + 9][col]);
        }
        // ---- A fragments via ldmatrix.x4, one per m16 tile ----
        #pragma unroll
        for (int tt = 0; tt < 4; ++tt) {
            const int rr = wm + tt * 16;
            uint32_t a0, a1, a2, a3;
            const uint32_t aaddr = asBase +
                ((uint32_t)(cur * 128 + rr + ldrow) * ASTRH + ldcol) * 2u;
            ldsm4(a0, a1, a2, a3, aaddr);
            #pragma unroll
            for (int u = 0; u < 4; ++u)
                mma_f16(acc[tt][u][0], acc[tt][u][1], acc[tt][u][2], acc[tt][u][3],
                        a0, a1, a2, a3, bf[u][0], bf[u][1]);
        }
        __syncthreads();
    }

    // ---- epilogue ----
    #pragma unroll
    for (int t = 0; t < 4; ++t) {
        #pragma unroll
        for (int u = 0; u < 4; ++u) {
            const int m = m0 + wm + t*16 + gid;
            const int n = n0 + wn + u*8 + tig*2;
            float v0 = acc[t][u][0], v1 = acc[t][u][1];
            float v2 = acc[t][u][2], v3 = acc[t][u][3];
            if (MODE >= 1) {
                float b0 = bias[n], b1 = bias[n+1];
                v0 += b0; v1 += b1; v2 += b0; v3 += b1;
            }
            if (MODE == 1) {
                v0 = fmaxf(v0, 0.f); v1 = fmaxf(v1, 0.f);
                v2 = fmaxf(v2, 0.f); v3 = fmaxf(v3, 0.f);
                __half* Ch = (__half*)C;
                *(__half2*)(Ch + (size_t)m * N + n)     = __floats2half2_rn(v0, v1);
                *(__half2*)(Ch + (size_t)(m+8) * N + n) = __floats2half2_rn(v2, v3);
            } else {
                if (MODE == 2) {
                    const float2 r0 = *(const float2*)(res + (size_t)m * N + n);
                    const float2 r1 = *(const float2*)(res + (size_t)(m+8) * N + n);
                    v0 += r0.x; v1 += r0.y; v2 += r1.x; v3 += r1.y;
                }
                *(float2*)(C + (size_t)m * N + n)       = make_float2(v0, v1);
                *(float2*)(C + (size_t)(m+8) * N + n)   = make_float2(v2, v3);
            }
        }
    }
}

// ---------------- Flash attention (R7/R8 exact): static smem, 128 thr, 64-row CTA ----------------
__global__ __launch_bounds__(128) void flash_kernel(const float* __restrict__ embds,
                                                    float* __restrict__ out)
{
    __shared__ float Qs[64][68];
    __shared__ float Ks[32][68];
    __shared__ float Vs[32][72];
    __shared__ float Ps[64][36];

    const int it = gridDim.x - 1 - blockIdx.x;   // heavy tiles first
    const int bh = blockIdx.y;
    const int b = bh >> 4, h = bh & 15;
    const int tid = threadIdx.x, warp = tid >> 5, lane = tid & 31;
    const int gid = lane >> 2, tig = lane & 3;
    const int i0 = it * 64;
    const int wr = i0 + warp * 16;

    #pragma unroll
    for (int l = 0; l < 8; ++l) {
        int idx = l * 128 + tid;
        int r = idx >> 4, e4 = (idx & 15) * 4;
        float4 qv = *(const float4*)(g_q + (((size_t)(b*T_ + i0 + r))*H_ + h)*HS_ + e4);
        qv.x = f2tf(qv.x); qv.y = f2tf(qv.y); qv.z = f2tf(qv.z); qv.w = f2tf(qv.w);
        *(float4*)(&Qs[r][e4]) = qv;
    }

    float oacc[8][4];
    #pragma unroll
    for (int u = 0; u < 8; ++u)
        #pragma unroll
        for (int c = 0; c < 4; ++c) oacc[u][c] = 0.f;
    float mrow[2] = {-1e30f, -1e30f};
    float lrow[2] = {0.f, 0.f};

    const int njc = 2*it + 2;
    for (int jc = 0; jc < njc; ++jc) {
        const int j0 = jc * 32;
        __syncthreads();
        #pragma unroll
        for (int l = 0; l < 4; ++l) {
            int idx = l * 128 + tid;
            int r = idx >> 4, e4 = (idx & 15) * 4;
            const size_t grow = (((size_t)(b*T_ + j0 + r))*H_ + h)*HS_ + e4;
            float4 kv = *(const float4*)(g_k + grow);
            kv.x = f2tf(kv.x); kv.y = f2tf(kv.y); kv.z = f2tf(kv.z); kv.w = f2tf(kv.w);
            *(float4*)(&Ks[r][e4]) = kv;
            float4 vv = *(const float4*)(g_v + grow);
            vv.x = f2tf(vv.x); vv.y = f2tf(vv.y); vv.z = f2tf(vv.z); vv.w = f2tf(vv.w);
            *(float4*)(&Vs[r][e4]) = vv;
        }
        __syncthreads();

        if (j0 <= wr + 15) {
            float sacc[4][4];
            #pragma unroll
            for (int u = 0; u < 4; ++u)
                #pragma unroll
                for (int c = 0; c < 4; ++c) sacc[u][c] = 0.f;
            #pragma unroll
            for (int kc = 0; kc < 8; ++kc) {
                const int kb = kc * 8;
                float a0 = Qs[warp*16 + gid    ][kb + tig];
                float a1 = Qs[warp*16 + gid + 8][kb + tig];
                float a2 = Qs[warp*16 + gid    ][kb + tig + 4];
                float a3 = Qs[warp*16 + gid + 8][kb + tig + 4];
                #pragma unroll
                for (int u = 0; u < 4; ++u) {
                    float b0 = Ks[u*8 + gid][kb + tig];
                    float b1 = Ks[u*8 + gid][kb + tig + 4];
                    mma_tf32(sacc[u][0], sacc[u][1], sacc[u][2], sacc[u][3],
                             a0, a1, a2, a3, b0, b1);
                }
            }

            const bool maskneed = (j0 + 31 > wr);
            #pragma unroll
            for (int rh = 0; rh < 2; ++rh) {
                const int row = wr + gid + rh*8;
                float tmax = -1e30f;
                #pragma unroll
                for (int u = 0; u < 4; ++u) {
                    float x0 = sacc[u][rh*2    ] * 0.03125f;
                    float x1 = sacc[u][rh*2 + 1] * 0.03125f;
                    if (maskneed) {
                        const int c = j0 + u*8 + tig*2;
                        if (c     > row) x0 = -1e30f;
                        if (c + 1 > row) x1 = -1e30f;
                    }
                    sacc[u][rh*2    ] = x0;
                    sacc[u][rh*2 + 1] = x1;
                    tmax = fmaxf(tmax, fmaxf(x0, x1));
                }
                tmax = fmaxf(tmax, __shfl_xor_sync(0xffffffffu, tmax, 1));
                tmax = fmaxf(tmax, __shfl_xor_sync(0xffffffffu, tmax, 2));
                const float mnew = fmaxf(mrow[rh], tmax);
                const float corr = __expf(mrow[rh] - mnew);
                float rsum = 0.f;
                #pragma unroll
                for (int u = 0; u < 4; ++u) {
                    float p0 = __expf(sacc[u][rh*2    ] - mnew);
                    float p1 = __expf(sacc[u][rh*2 + 1] - mnew);
                    rsum += p0 + p1;
                    *(float2*)(&Ps[warp*16 + gid + rh*8][u*8 + tig*2]) =
                        make_float2(f2tf(p0), f2tf(p1));
                }
                #pragma unroll
                for (int uu = 0; uu < 8; ++uu) {
                    oacc[uu][rh*2    ] *= corr;
                    oacc[uu][rh*2 + 1] *= corr;
                }
                rsum += __shfl_xor_sync(0xffffffffu, rsum, 1);
                rsum += __shfl_xor_sync(0xffffffffu, rsum, 2);
                lrow[rh] = lrow[rh] * corr + rsum;
                mrow[rh] = mnew;
            }
            __syncwarp();

            #pragma unroll
            for (int kc = 0; kc < 4; ++kc) {
                const int kb = kc * 8;
                float a0 = Ps[warp*16 + gid    ][kb + tig];
                float a1 = Ps[warp*16 + gid + 8][kb + tig];
                float a2 = Ps[warp*16 + gid    ][kb + tig + 4];
                float a3 = Ps[warp*16 + gid + 8][kb + tig + 4];
                #pragma unroll
                for (int u = 0; u < 8; ++u) {
                    float b0 = Vs[kb + tig    ][u*8 + gid];
                    float b1 = Vs[kb + tig + 4][u*8 + gid];
                    mma_tf32(oacc[u][0], oacc[u][1], oacc[u][2], oacc[u][3],
                             a0, a1, a2, a3, b0, b1);
                }
            }
        }
    }

    #pragma unroll
    for (int rh = 0; rh < 2; ++rh) {
        const int t = wr + gid + rh*8;
        const float inv = 1.0f / lrow[rh];
        #pragma unroll
        for (int u = 0; u < 8; ++u) {
            const int d = h * HS_ + u*8 + tig*2;
            const size_t o = ((size_t)(b*T_ + t))*D_ + d;
            const float2 e = *(const float2*)(embds + o);
            *(float2*)(out + o) = make_float2(e.x + oacc[u][rh*2    ]*inv,
                                              e.y + oacc[u][rh*2 + 1]*inv);
        }
    }
}

// ---------------- Launcher ----------------
extern "C" void kernel_launch(void* const* d_in, const int* in_sizes, int n_in,
                              void* d_out, int out_size)
{
    const float* embds = (const float*)d_in[0];
    const float* Wq    = (const float*)d_in[1];
    const float* Wk    = (const float*)d_in[2];
    const float* Wv    = (const float*)d_in[3];
    const float* ln1g  = (const float*)d_in[4];
    const float* ln1b  = (const float*)d_in[5];
    const float* ln2g  = (const float*)d_in[6];
    const float* ln2b  = (const float*)d_in[7];
    const float* W1    = (const float*)d_in[8];
    const float* b1    = (const float*)d_in[9];
    const float* W2    = (const float*)d_in[10];
    const float* b2    = (const float*)d_in[11];
    float* out = (float*)d_out;

    __half *xh, *fh;
    float *q, *k, *v, *res1;
    cudaGetSymbolAddress((void**)&xh,   g_xh);
    cudaGetSymbolAddress((void**)&fh,   g_fh);
    cudaGetSymbolAddress((void**)&q,    g_q);
    cudaGetSymbolAddress((void**)&k,    g_k);
    cudaGetSymbolAddress((void**)&v,    g_v);
    cudaGetSymbolAddress((void**)&res1, g_res1);

    // 1. LN1 -> fp16
    ln_kernel<<<BT_, 256>>>(embds, ln1g, ln1b, xh);

    // 2. Fused QKV via gridDim.z -> q,k,v [B,T,H,HS] fp32
    tgemm_kernel<0><<<dim3(D_/128, BT_/128, 3), 256>>>(
        xh, Wq, Wk, Wv, nullptr, nullptr, q, k, v, BT_, D_, D_);

    // 3. Flash attention + head-concat + residual -> res1
    flash_kernel<<<dim3(T_/64, BH_), 128>>>(embds, res1);

    // 4. LN2 -> fp16
    ln_kernel<<<BT_, 256>>>(res1, ln2g, ln2b, xh);

    // 5. FFN1: relu(y @ W1 + b1) -> fp16 ffh
    tgemm_kernel<1><<<dim3(4*D_/128, BT_/128), 256>>>(
        xh, W1, nullptr, nullptr, b1, nullptr, (float*)fh, nullptr, nullptr, BT_, 4*D_, D_);

    // 6. FFN2: ffh @ W2 + b2 + res1 -> out
    tgemm_kernel<2><<<dim3(D_/128, BT_/128), 256>>>(
        fh, W2, nullptr, nullptr, b2, res1, out, nullptr, nullptr, BT_, D_, 4*D_);
}

// round 12
// speedup vs baseline: 1.5847x; 1.2232x over previous
#include <cuda_runtime.h>
#include <cuda_fp16.h>
#include <math.h>
#include <stdint.h>

// ---------------- Problem dims ----------------
#define B_  2
#define T_  2048
#define D_  1024
#define H_  16
#define HS_ 64
#define BT_ (B_*T_)      // 4096
#define BH_ (B_*H_)      // 32
#define EPS_ 1e-5f

// ---------------- Scratch (static device memory; no allocations) ----------------
__device__ __align__(16) __half g_xh [BT_*D_];            // LN out, fp16 (GEMM A-side only)
__device__ __align__(16) __half g_fh [(size_t)BT_*4*D_];  // FFN1 out, fp16 (GEMM A-side only)
__device__ __align__(16) float  g_q  [BT_*D_];            // [B,T,H,HS]
__device__ __align__(16) float  g_k  [BT_*D_];
__device__ __align__(16) float  g_v  [BT_*D_];
__device__ __align__(16) float  g_res1[BT_*D_];

// ---------------- Helpers ----------------
__device__ __forceinline__ float f2tf(float f) {
    uint32_t r;
    asm("cvt.rna.tf32.f32 %0, %1;" : "=r"(r) : "f"(f));
    return __uint_as_float(r);
}
__device__ __forceinline__ void mma_tf32(float& c0, float& c1, float& c2, float& c3,
                                         float a0, float a1, float a2, float a3,
                                         float b0, float b1)
{
    uint32_t ua0 = __float_as_uint(a0), ua1 = __float_as_uint(a1);
    uint32_t ua2 = __float_as_uint(a2), ua3 = __float_as_uint(a3);
    uint32_t ub0 = __float_as_uint(b0), ub1 = __float_as_uint(b1);
    asm volatile("mma.sync.aligned.m16n8k8.row.col.f32.tf32.tf32.f32 "
                 "{%0,%1,%2,%3}, {%4,%5,%6,%7}, {%8,%9}, {%0,%1,%2,%3};"
                 : "+f"(c0), "+f"(c1), "+f"(c2), "+f"(c3)
                 : "r"(ua0), "r"(ua1), "r"(ua2), "r"(ua3), "r"(ub0), "r"(ub1));
}
__device__ __forceinline__ uint32_t pk16(float lo, float hi) {
    uint32_t d;
    asm("cvt.rn.f16x2.f32 %0, %1, %2;" : "=r"(d) : "f"(hi), "f"(lo));
    return d;
}
__device__ __forceinline__ void mma_f16(float& c0, float& c1, float& c2, float& c3,
                                        uint32_t a0, uint32_t a1, uint32_t a2, uint32_t a3,
                                        uint32_t b0, uint32_t b1)
{
    asm volatile("mma.sync.aligned.m16n8k16.row.col.f32.f16.f16.f32 "
                 "{%0,%1,%2,%3}, {%4,%5,%6,%7}, {%8,%9}, {%0,%1,%2,%3};"
                 : "+f"(c0), "+f"(c1), "+f"(c2), "+f"(c3)
                 : "r"(a0), "r"(a1), "r"(a2), "r"(a3), "r"(b0), "r"(b1));
}
__device__ __forceinline__ void cp16(void* s, const void* g) {
    uint32_t sa = (uint32_t)__cvta_generic_to_shared(s);
    asm volatile("cp.async.cg.shared.global [%0], [%1], 16;" :: "r"(sa), "l"(g));
}
__device__ __forceinline__ void cp_commit() { asm volatile("cp.async.commit_group;" ::: "memory"); }
template<int N>
__device__ __forceinline__ void cp_wait() { asm volatile("cp.async.wait_group %0;" :: "n"(N) : "memory"); }
__device__ __forceinline__ void ldsm4(uint32_t& a0, uint32_t& a1, uint32_t& a2, uint32_t& a3,
                                      uint32_t addr)
{
    asm volatile("ldmatrix.sync.aligned.m8n8.x4.shared.b16 {%0,%1,%2,%3}, [%4];"
                 : "=r"(a0), "=r"(a1), "=r"(a2), "=r"(a3) : "r"(addr));
}
__device__ __forceinline__ void ldsm4t(uint32_t& a0, uint32_t& a1, uint32_t& a2, uint32_t& a3,
                                       uint32_t addr)
{
    asm volatile("ldmatrix.sync.aligned.m8n8.x4.trans.shared.b16 {%0,%1,%2,%3}, [%4];"
                 : "=r"(a0), "=r"(a1), "=r"(a2), "=r"(a3) : "r"(addr));
}

// ---------------- LayerNorm (fp16 output: feeds GEMM A-sides only) ----------------
__global__ __launch_bounds__(256) void ln_kernel(const float* __restrict__ x,
                                                 const float* __restrict__ gam,
                                                 const float* __restrict__ bet,
                                                 __half* __restrict__ y)
{
    const int row = blockIdx.x;
    const int tid = threadIdx.x;
    const float4 v = *(const float4*)(x + (size_t)row*D_ + tid*4);
    float s  = v.x + v.y + v.z + v.w;
    float s2 = v.x*v.x + v.y*v.y + v.z*v.z + v.w*v.w;
    __shared__ float shs[8], shs2[8], stat[2];
    #pragma unroll
    for (int o = 16; o; o >>= 1) {
        s  += __shfl_xor_sync(0xffffffffu, s,  o);
        s2 += __shfl_xor_sync(0xffffffffu, s2, o);
    }
    if ((tid & 31) == 0) { shs[tid >> 5] = s; shs2[tid >> 5] = s2; }
    __syncthreads();
    if (tid == 0) {
        float ts = 0.f, ts2 = 0.f;
        #pragma unroll
        for (int w = 0; w < 8; ++w) { ts += shs[w]; ts2 += shs2[w]; }
        float mean = ts * (1.0f / D_);
        float var  = ts2 * (1.0f / D_) - mean * mean;
        stat[0] = mean; stat[1] = rsqrtf(var + EPS_);
    }
    __syncthreads();
    const float mean = stat[0], rstd = stat[1];
    const float4 g4 = *(const float4*)(gam + tid*4);
    const float4 b4 = *(const float4*)(bet + tid*4);
    __half2 ha = __floats2half2_rn((v.x - mean) * rstd * g4.x + b4.x,
                                   (v.y - mean) * rstd * g4.y + b4.y);
    __half2 hb = __floats2half2_rn((v.z - mean) * rstd * g4.z + b4.z,
                                   (v.w - mean) * rstd * g4.w + b4.w);
    __half2* yp = (__half2*)(y + (size_t)row*D_ + tid*4);
    yp[0] = ha; yp[1] = hb;
}

// ---------------- fp16 GEMM: 128x128 tile, BK=16, m16n8k16, ldmatrix A+B ----------------
// A: fp16 global (producer-converted), cp.async to smem, ldmatrix.x4.
// B: fp32 weights, LDG one tile ahead -> pk16 -> fp16 smem -> ldmatrix.x4.trans.
// MODE 0: QKV (blockIdx.z selects W / output; MAPB layout, no bias)  -> fp32 out
// MODE 1: FFN1 (bias + relu)                                          -> fp16 out
// MODE 2: FFN2 (bias + residual)                                      -> fp32 out
#define ASTRH 24
#define BSTRH 136

template<int MODE>
__global__ __launch_bounds__(256) void tgemm_kernel(
    const __half* __restrict__ A,
    const float* __restrict__ B0, const float* __restrict__ B1, const float* __restrict__ B2,
    const float* __restrict__ bias, const float* __restrict__ res,
    float* __restrict__ C0, float* __restrict__ C1, float* __restrict__ C2,
    int M, int N, int K)
{
    __shared__ __align__(16) __half As[2][128][ASTRH];
    __shared__ __align__(16) __half Bsh[2][16][BSTRH];

    const float* Bm;
    float* C;
    if (MODE == 0) {
        Bm = (blockIdx.z == 0) ? B0 : (blockIdx.z == 1 ? B1 : B2);
        C  = (blockIdx.z == 0) ? C0 : (blockIdx.z == 1 ? C1 : C2);
    } else {
        Bm = B0;
        C  = C0;
    }

    const int tid  = threadIdx.x;
    const int m0 = blockIdx.y * 128, n0 = blockIdx.x * 128;
    const int warp = tid >> 5, lane = tid & 31;
    const int gid = lane >> 2, tig = lane & 3;
    const int wm = (warp >> 2) * 64;   // 0,64
    const int wn = (warp & 3) * 32;    // 0,32,64,96

    // ldmatrix per-lane coords (shared by A tiles and B 16x16 blocks)
    const int ldrow = (lane & 7) + ((lane >> 3) & 1) * 8;
    const int ldcol = (lane >> 4) * 8;
    const uint32_t asBase = (uint32_t)__cvta_generic_to_shared(&As[0][0][0]);
    const uint32_t bsBase = (uint32_t)__cvta_generic_to_shared(&Bsh[0][0][0]);

    // A fill: 1 x 16B per thread per tile (128 rows x 16 halves)
    const int lar = tid >> 1;
    const int lacH = (tid & 1) * 8;
    // B fill: 2 float4 per thread per tile (16 rows x 128 floats)
    const int lbk0 = (tid      ) >> 5, lbn0 = ((tid      ) & 31) * 4;
    const int lbk1 = (tid + 256) >> 5, lbn1 = ((tid + 256) & 31) * 4;

    const __half* Aread = A + (size_t)(m0 + lar) * K + lacH;

    float acc[4][4][4];
    #pragma unroll
    for (int t = 0; t < 4; ++t)
        #pragma unroll
        for (int u = 0; u < 4; ++u)
            #pragma unroll
            for (int c = 0; c < 4; ++c) acc[t][u][c] = 0.f;

    const int ntiles = K >> 4;   // always even (64 or 256)

#define LDG_B(DST0, DST1, TT) do { \
        if (MODE == 0) { \
            int c0_ = n0 + lbn0, c1_ = n0 + lbn1; \
            DST0 = *(const float4*)(Bm + ((size_t)(c0_ >> 6) * K + ((TT) << 4) + lbk0) * HS_ + (c0_ & 63)); \
            DST1 = *(const float4*)(Bm + ((size_t)(c1_ >> 6) * K + ((TT) << 4) + lbk1) * HS_ + (c1_ & 63)); \
        } else { \
            DST0 = *(const float4*)(Bm + (size_t)(((TT) << 4) + lbk0) * N + n0 + lbn0); \
            DST1 = *(const float4*)(Bm + (size_t)(((TT) << 4) + lbk1) * N + n0 + lbn1); \
        } \
    } while (0)

#define STS_B(NB, W0, W1) do { \
        *(uint2*)&Bsh[NB][lbk0][lbn0] = make_uint2(pk16(W0.x, W0.y), pk16(W0.z, W0.w)); \
        *(uint2*)&Bsh[NB][lbk1][lbn1] = make_uint2(pk16(W1.x, W1.y), pk16(W1.z, W1.w)); \
    } while (0)

#define GEMM_BODY(T, SW0, SW1, LW0, LW1) do { \
        cp_wait<0>(); \
        __syncthreads(); \
        const int cur_ = (T) & 1, nb_ = cur_ ^ 1; \
        if ((T) + 1 < ntiles) { \
            cp16(&As[nb_][lar][lacH], Aread + (((T) + 1) << 4)); \
            cp_commit(); \
            STS_B(nb_, SW0, SW1); \
        } \
        if ((T) + 2 < ntiles) { LDG_B(LW0, LW1, (T) + 2); } \
        /* B fragments: 2x ldmatrix.x4.trans */ \
        uint32_t bfr[8]; \
        { \
            const uint32_t bAddr = bsBase + \
                ((uint32_t)(cur_ * 16 + ldrow) * BSTRH + wn + ldcol) * 2u; \
            ldsm4t(bfr[0], bfr[1], bfr[2], bfr[3], bAddr); \
            ldsm4t(bfr[4], bfr[5], bfr[6], bfr[7], bAddr + 32u); \
        } \
        _Pragma("unroll") \
        for (int tt = 0; tt < 4; ++tt) { \
            const int rr = wm + tt * 16; \
            uint32_t a0, a1, a2, a3; \
            const uint32_t aAddr = asBase + \
                ((uint32_t)(cur_ * 128 + rr + ldrow) * ASTRH + ldcol) * 2u; \
            ldsm4(a0, a1, a2, a3, aAddr); \
            _Pragma("unroll") \
            for (int u = 0; u < 4; ++u) \
                mma_f16(acc[tt][u][0], acc[tt][u][1], acc[tt][u][2], acc[tt][u][3], \
                        a0, a1, a2, a3, bfr[u*2], bfr[u*2 + 1]); \
        } \
    } while (0)

    // ---- prologue ----
    float4 wA0, wA1, wB0, wB1;
    cp16(&As[0][lar][lacH], Aread);
    cp_commit();
    LDG_B(wA0, wA1, 0);
    STS_B(0, wA0, wA1);
    if (ntiles > 1) { LDG_B(wA0, wA1, 1); }

    for (int t = 0; t < ntiles; t += 2) {
        GEMM_BODY(t,     wA0, wA1, wB0, wB1);
        GEMM_BODY(t + 1, wB0, wB1, wA0, wA1);
    }

#undef GEMM_BODY
#undef STS_B
#undef LDG_B

    // ---- epilogue ----
    #pragma unroll
    for (int t = 0; t < 4; ++t) {
        #pragma unroll
        for (int u = 0; u < 4; ++u) {
            const int m = m0 + wm + t*16 + gid;
            const int n = n0 + wn + u*8 + tig*2;
            float v0 = acc[t][u][0], v1 = acc[t][u][1];
            float v2 = acc[t][u][2], v3 = acc[t][u][3];
            if (MODE >= 1) {
                float b0 = bias[n], b1 = bias[n+1];
                v0 += b0; v1 += b1; v2 += b0; v3 += b1;
            }
            if (MODE == 1) {
                v0 = fmaxf(v0, 0.f); v1 = fmaxf(v1, 0.f);
                v2 = fmaxf(v2, 0.f); v3 = fmaxf(v3, 0.f);
                __half* Ch = (__half*)C;
                *(__half2*)(Ch + (size_t)m * N + n)     = __floats2half2_rn(v0, v1);
                *(__half2*)(Ch + (size_t)(m+8) * N + n) = __floats2half2_rn(v2, v3);
            } else {
                if (MODE == 2) {
                    const float2 r0 = *(const float2*)(res + (size_t)m * N + n);
                    const float2 r1 = *(const float2*)(res + (size_t)(m+8) * N + n);
                    v0 += r0.x; v1 += r0.y; v2 += r1.x; v3 += r1.y;
                }
                *(float2*)(C + (size_t)m * N + n)       = make_float2(v0, v1);
                *(float2*)(C + (size_t)(m+8) * N + n)   = make_float2(v2, v3);
            }
        }
    }
}

// ---------------- Flash attention (R7/R8/R11 exact): static smem, 128 thr, 64-row CTA ----------------
__global__ __launch_bounds__(128) void flash_kernel(const float* __restrict__ embds,
                                                    float* __restrict__ out)
{
    __shared__ float Qs[64][68];
    __shared__ float Ks[32][68];
    __shared__ float Vs[32][72];
    __shared__ float Ps[64][36];

    const int it = gridDim.x - 1 - blockIdx.x;   // heavy tiles first
    const int bh = blockIdx.y;
    const int b = bh >> 4, h = bh & 15;
    const int tid = threadIdx.x, warp = tid >> 5, lane = tid & 31;
    const int gid = lane >> 2, tig = lane & 3;
    const int i0 = it * 64;
    const int wr = i0 + warp * 16;

    #pragma unroll
    for (int l = 0; l < 8; ++l) {
        int idx = l * 128 + tid;
        int r = idx >> 4, e4 = (idx & 15) * 4;
        float4 qv = *(const float4*)(g_q + (((size_t)(b*T_ + i0 + r))*H_ + h)*HS_ + e4);
        qv.x = f2tf(qv.x); qv.y = f2tf(qv.y); qv.z = f2tf(qv.z); qv.w = f2tf(qv.w);
        *(float4*)(&Qs[r][e4]) = qv;
    }

    float oacc[8][4];
    #pragma unroll
    for (int u = 0; u < 8; ++u)
        #pragma unroll
        for (int c = 0; c < 4; ++c) oacc[u][c] = 0.f;
    float mrow[2] = {-1e30f, -1e30f};
    float lrow[2] = {0.f, 0.f};

    const int njc = 2*it + 2;
    for (int jc = 0; jc < njc; ++jc) {
        const int j0 = jc * 32;
        __syncthreads();
        #pragma unroll
        for (int l = 0; l < 4; ++l) {
            int idx = l * 128 + tid;
            int r = idx >> 4, e4 = (idx & 15) * 4;
            const size_t grow = (((size_t)(b*T_ + j0 + r))*H_ + h)*HS_ + e4;
            float4 kv = *(const float4*)(g_k + grow);
            kv.x = f2tf(kv.x); kv.y = f2tf(kv.y); kv.z = f2tf(kv.z); kv.w = f2tf(kv.w);
            *(float4*)(&Ks[r][e4]) = kv;
            float4 vv = *(const float4*)(g_v + grow);
            vv.x = f2tf(vv.x); vv.y = f2tf(vv.y); vv.z = f2tf(vv.z); vv.w = f2tf(vv.w);
            *(float4*)(&Vs[r][e4]) = vv;
        }
        __syncthreads();

        if (j0 <= wr + 15) {
            float sacc[4][4];
            #pragma unroll
            for (int u = 0; u < 4; ++u)
                #pragma unroll
                for (int c = 0; c < 4; ++c) sacc[u][c] = 0.f;
            #pragma unroll
            for (int kc = 0; kc < 8; ++kc) {
                const int kb = kc * 8;
                float a0 = Qs[warp*16 + gid    ][kb + tig];
                float a1 = Qs[warp*16 + gid + 8][kb + tig];
                float a2 = Qs[warp*16 + gid    ][kb + tig + 4];
                float a3 = Qs[warp*16 + gid + 8][kb + tig + 4];
                #pragma unroll
                for (int u = 0; u < 4; ++u) {
                    float b0 = Ks[u*8 + gid][kb + tig];
                    float b1 = Ks[u*8 + gid][kb + tig + 4];
                    mma_tf32(sacc[u][0], sacc[u][1], sacc[u][2], sacc[u][3],
                             a0, a1, a2, a3, b0, b1);
                }
            }

            const bool maskneed = (j0 + 31 > wr);
            #pragma unroll
            for (int rh = 0; rh < 2; ++rh) {
                const int row = wr + gid + rh*8;
                float tmax = -1e30f;
                #pragma unroll
                for (int u = 0; u < 4; ++u) {
                    float x0 = sacc[u][rh*2    ] * 0.03125f;
                    float x1 = sacc[u][rh*2 + 1] * 0.03125f;
                    if (maskneed) {
                        const int c = j0 + u*8 + tig*2;
                        if (c     > row) x0 = -1e30f;
                        if (c + 1 > row) x1 = -1e30f;
                    }
                    sacc[u][rh*2    ] = x0;
                    sacc[u][rh*2 + 1] = x1;
                    tmax = fmaxf(tmax, fmaxf(x0, x1));
                }
                tmax = fmaxf(tmax, __shfl_xor_sync(0xffffffffu, tmax, 1));
                tmax = fmaxf(tmax, __shfl_xor_sync(0xffffffffu, tmax, 2));
                const float mnew = fmaxf(mrow[rh], tmax);
                const float corr = __expf(mrow[rh] - mnew);
                float rsum = 0.f;
                #pragma unroll
                for (int u = 0; u < 4; ++u) {
                    float p0 = __expf(sacc[u][rh*2    ] - mnew);
                    float p1 = __expf(sacc[u][rh*2 + 1] - mnew);
                    rsum += p0 + p1;
                    *(float2*)(&Ps[warp*16 + gid + rh*8][u*8 + tig*2]) =
                        make_float2(f2tf(p0), f2tf(p1));
                }
                #pragma unroll
                for (int uu = 0; uu < 8; ++uu) {
                    oacc[uu][rh*2    ] *= corr;
                    oacc[uu][rh*2 + 1] *= corr;
                }
                rsum += __shfl_xor_sync(0xffffffffu, rsum, 1);
                rsum += __shfl_xor_sync(0xffffffffu, rsum, 2);
                lrow[rh] = lrow[rh] * corr + rsum;
                mrow[rh] = mnew;
            }
            __syncwarp();

            #pragma unroll
            for (int kc = 0; kc < 4; ++kc) {
                const int kb = kc * 8;
                float a0 = Ps[warp*16 + gid    ][kb + tig];
                float a1 = Ps[warp*16 + gid + 8][kb + tig];
                float a2 = Ps[warp*16 + gid    ][kb + tig + 4];
                float a3 = Ps[warp*16 + gid + 8][kb + tig + 4];
                #pragma unroll
                for (int u = 0; u < 8; ++u) {
                    float b0 = Vs[kb + tig    ][u*8 + gid];
                    float b1 = Vs[kb + tig + 4][u*8 + gid];
                    mma_tf32(oacc[u][0], oacc[u][1], oacc[u][2], oacc[u][3],
                             a0, a1, a2, a3, b0, b1);
                }
            }
        }
    }

    #pragma unroll
    for (int rh = 0; rh < 2; ++rh) {
        const int t = wr + gid + rh*8;
        const float inv = 1.0f / lrow[rh];
        #pragma unroll
        for (int u = 0; u < 8; ++u) {
            const int d = h * HS_ + u*8 + tig*2;
            const size_t o = ((size_t)(b*T_ + t))*D_ + d;
            const float2 e = *(const float2*)(embds + o);
            *(float2*)(out + o) = make_float2(e.x + oacc[u][rh*2    ]*inv,
                                              e.y + oacc[u][rh*2 + 1]*inv);
        }
    }
}

// ---------------- Launcher ----------------
extern "C" void kernel_launch(void* const* d_in, const int* in_sizes, int n_in,
                              void* d_out, int out_size)
{
    const float* embds = (const float*)d_in[0];
    const float* Wq    = (const float*)d_in[1];
    const float* Wk    = (const float*)d_in[2];
    const float* Wv    = (const float*)d_in[3];
    const float* ln1g  = (const float*)d_in[4];
    const float* ln1b  = (const float*)d_in[5];
    const float* ln2g  = (const float*)d_in[6];
    const float* ln2b  = (const float*)d_in[7];
    const float* W1    = (const float*)d_in[8];
    const float* b1    = (const float*)d_in[9];
    const float* W2    = (const float*)d_in[10];
    const float* b2    = (const float*)d_in[11];
    float* out = (float*)d_out;

    __half *xh, *fh;
    float *q, *k, *v, *res1;
    cudaGetSymbolAddress((void**)&xh,   g_xh);
    cudaGetSymbolAddress((void**)&fh,   g_fh);
    cudaGetSymbolAddress((void**)&q,    g_q);
    cudaGetSymbolAddress((void**)&k,    g_k);
    cudaGetSymbolAddress((void**)&v,    g_v);
    cudaGetSymbolAddress((void**)&res1, g_res1);

    // 1. LN1 -> fp16
    ln_kernel<<<BT_, 256>>>(embds, ln1g, ln1b, xh);

    // 2. Fused QKV via gridDim.z -> q,k,v [B,T,H,HS] fp32
    tgemm_kernel<0><<<dim3(D_/128, BT_/128, 3), 256>>>(
        xh, Wq, Wk, Wv, nullptr, nullptr, q, k, v, BT_, D_, D_);

    // 3. Flash attention + head-concat + residual -> res1
    flash_kernel<<<dim3(T_/64, BH_), 128>>>(embds, res1);

    // 4. LN2 -> fp16
    ln_kernel<<<BT_, 256>>>(res1, ln2g, ln2b, xh);

    // 5. FFN1: relu(y @ W1 + b1) -> fp16 ffh
    tgemm_kernel<1><<<dim3(4*D_/128, BT_/128), 256>>>(
        xh, W1, nullptr, nullptr, b1, nullptr, (float*)fh, nullptr, nullptr, BT_, 4*D_, D_);

    // 6. FFN2: ffh @ W2 + b2 + res1 -> out
    tgemm_kernel<2><<<dim3(D_/128, BT_/128), 256>>>(
        fh, W2, nullptr, nullptr, b2, res1, out, nullptr, nullptr, BT_, D_, 4*D_);
}

// round 13
// speedup vs baseline: 1.7803x; 1.1234x over previous
#include <cuda_runtime.h>
#include <cuda_fp16.h>
#include <math.h>
#include <stdint.h>

// ---------------- Problem dims ----------------
#define B_  2
#define T_  2048
#define D_  1024
#define H_  16
#define HS_ 64
#define BT_ (B_*T_)      // 4096
#define BH_ (B_*H_)      // 32
#define EPS_ 1e-5f

// ---------------- Scratch (static device memory; no allocations) ----------------
__device__ __align__(16) __half g_xh [BT_*D_];            // LN out, fp16
__device__ __align__(16) __half g_fh [(size_t)BT_*4*D_];  // FFN1 out, fp16
__device__ __align__(16) __half g_qh [BT_*D_];            // [B,T,H,HS] fp16
__device__ __align__(16) __half g_kh [BT_*D_];
__device__ __align__(16) __half g_vh [BT_*D_];
__device__ __align__(16) float  g_res1[BT_*D_];

// ---------------- Helpers ----------------
__device__ __forceinline__ uint32_t pk16(float lo, float hi) {
    uint32_t d;
    asm("cvt.rn.f16x2.f32 %0, %1, %2;" : "=r"(d) : "f"(hi), "f"(lo));
    return d;
}
__device__ __forceinline__ void mma_f16(float& c0, float& c1, float& c2, float& c3,
                                        uint32_t a0, uint32_t a1, uint32_t a2, uint32_t a3,
                                        uint32_t b0, uint32_t b1)
{
    asm volatile("mma.sync.aligned.m16n8k16.row.col.f32.f16.f16.f32 "
                 "{%0,%1,%2,%3}, {%4,%5,%6,%7}, {%8,%9}, {%0,%1,%2,%3};"
                 : "+f"(c0), "+f"(c1), "+f"(c2), "+f"(c3)
                 : "r"(a0), "r"(a1), "r"(a2), "r"(a3), "r"(b0), "r"(b1));
}
__device__ __forceinline__ void cp16(void* s, const void* g) {
    uint32_t sa = (uint32_t)__cvta_generic_to_shared(s);
    asm volatile("cp.async.cg.shared.global [%0], [%1], 16;" :: "r"(sa), "l"(g));
}
__device__ __forceinline__ void cp_commit() { asm volatile("cp.async.commit_group;" ::: "memory"); }
template<int N>
__device__ __forceinline__ void cp_wait() { asm volatile("cp.async.wait_group %0;" :: "n"(N) : "memory"); }
__device__ __forceinline__ void ldsm4(uint32_t& a0, uint32_t& a1, uint32_t& a2, uint32_t& a3,
                                      uint32_t addr)
{
    asm volatile("ldmatrix.sync.aligned.m8n8.x4.shared.b16 {%0,%1,%2,%3}, [%4];"
                 : "=r"(a0), "=r"(a1), "=r"(a2), "=r"(a3) : "r"(addr));
}
__device__ __forceinline__ void ldsm4t(uint32_t& a0, uint32_t& a1, uint32_t& a2, uint32_t& a3,
                                       uint32_t addr)
{
    asm volatile("ldmatrix.sync.aligned.m8n8.x4.trans.shared.b16 {%0,%1,%2,%3}, [%4];"
                 : "=r"(a0), "=r"(a1), "=r"(a2), "=r"(a3) : "r"(addr));
}

// ---------------- LayerNorm (fp16 output) ----------------
__global__ __launch_bounds__(256) void ln_kernel(const float* __restrict__ x,
                                                 const float* __restrict__ gam,
                                                 const float* __restrict__ bet,
                                                 __half* __restrict__ y)
{
    const int row = blockIdx.x;
    const int tid = threadIdx.x;
    const float4 v = *(const float4*)(x + (size_t)row*D_ + tid*4);
    float s  = v.x + v.y + v.z + v.w;
    float s2 = v.x*v.x + v.y*v.y + v.z*v.z + v.w*v.w;
    __shared__ float shs[8], shs2[8], stat[2];
    #pragma unroll
    for (int o = 16; o; o >>= 1) {
        s  += __shfl_xor_sync(0xffffffffu, s,  o);
        s2 += __shfl_xor_sync(0xffffffffu, s2, o);
    }
    if ((tid & 31) == 0) { shs[tid >> 5] = s; shs2[tid >> 5] = s2; }
    __syncthreads();
    if (tid == 0) {
        float ts = 0.f, ts2 = 0.f;
        #pragma unroll
        for (int w = 0; w < 8; ++w) { ts += shs[w]; ts2 += shs2[w]; }
        float mean = ts * (1.0f / D_);
        float var  = ts2 * (1.0f / D_) - mean * mean;
        stat[0] = mean; stat[1] = rsqrtf(var + EPS_);
    }
    __syncthreads();
    const float mean = stat[0], rstd = stat[1];
    const float4 g4 = *(const float4*)(gam + tid*4);
    const float4 b4 = *(const float4*)(bet + tid*4);
    __half2 ha = __floats2half2_rn((v.x - mean) * rstd * g4.x + b4.x,
                                   (v.y - mean) * rstd * g4.y + b4.y);
    __half2 hb = __floats2half2_rn((v.z - mean) * rstd * g4.z + b4.z,
                                   (v.w - mean) * rstd * g4.w + b4.w);
    __half2* yp = (__half2*)(y + (size_t)row*D_ + tid*4);
    yp[0] = ha; yp[1] = hb;
}

// ---------------- fp16 GEMM: 128x128 tile, BK=16, 3-stage A pipeline ----------------
// MODE 0: QKV (z-select; MAPB layout, no bias) -> fp16 out
// MODE 1: FFN1 (bias + relu)                   -> fp16 out
// MODE 2: FFN2 (bias + residual)               -> fp32 out
#define ASTRH 24
#define BSTRH 136

template<int MODE>
__global__ __launch_bounds__(256) void tgemm_kernel(
    const __half* __restrict__ A,
    const float* __restrict__ B0, const float* __restrict__ B1, const float* __restrict__ B2,
    const float* __restrict__ bias, const float* __restrict__ res,
    void* __restrict__ C0, void* __restrict__ C1, void* __restrict__ C2,
    int M, int N, int K)
{
    __shared__ __align__(16) __half As[3][128][ASTRH];
    __shared__ __align__(16) __half Bsh[2][16][BSTRH];

    const float* Bm;
    void* Cv;
    if (MODE == 0) {
        Bm = (blockIdx.z == 0) ? B0 : (blockIdx.z == 1 ? B1 : B2);
        Cv = (blockIdx.z == 0) ? C0 : (blockIdx.z == 1 ? C1 : C2);
    } else {
        Bm = B0;
        Cv = C0;
    }

    const int tid  = threadIdx.x;
    const int m0 = blockIdx.y * 128, n0 = blockIdx.x * 128;
    const int warp = tid >> 5, lane = tid & 31;
    const int gid = lane >> 2, tig = lane & 3;
    const int wm = (warp >> 2) * 64;   // 0,64
    const int wn = (warp & 3) * 32;    // 0,32,64,96

    const int ldrow = (lane & 7) + ((lane >> 3) & 1) * 8;
    const int ldcol = (lane >> 4) * 8;
    const uint32_t asBase = (uint32_t)__cvta_generic_to_shared(&As[0][0][0]);
    const uint32_t bsBase = (uint32_t)__cvta_generic_to_shared(&Bsh[0][0][0]);

    // A fill: 1 x 16B per thread per tile
    const int lar = tid >> 1;
    const int lacH = (tid & 1) * 8;
    // B fill: 2 float4 per thread per tile
    const int lbk0 = (tid      ) >> 5, lbn0 = ((tid      ) & 31) * 4;
    const int lbk1 = (tid + 256) >> 5, lbn1 = ((tid + 256) & 31) * 4;

    const __half* Aread = A + (size_t)(m0 + lar) * K + lacH;

    float acc[4][4][4];
    #pragma unroll
    for (int t = 0; t < 4; ++t)
        #pragma unroll
        for (int u = 0; u < 4; ++u)
            #pragma unroll
            for (int c = 0; c < 4; ++c) acc[t][u][c] = 0.f;

    const int ntiles = K >> 4;   // 64 or 256 (even)

#define LDG_B(DST0, DST1, TT) do { \
        if (MODE == 0) { \
            int c0_ = n0 + lbn0, c1_ = n0 + lbn1; \
            DST0 = *(const float4*)(Bm + ((size_t)(c0_ >> 6) * K + ((TT) << 4) + lbk0) * HS_ + (c0_ & 63)); \
            DST1 = *(const float4*)(Bm + ((size_t)(c1_ >> 6) * K + ((TT) << 4) + lbk1) * HS_ + (c1_ & 63)); \
        } else { \
            DST0 = *(const float4*)(Bm + (size_t)(((TT) << 4) + lbk0) * N + n0 + lbn0); \
            DST1 = *(const float4*)(Bm + (size_t)(((TT) << 4) + lbk1) * N + n0 + lbn1); \
        } \
    } while (0)

#define STS_B(NB, W0, W1) do { \
        *(uint2*)&Bsh[NB][lbk0][lbn0] = make_uint2(pk16(W0.x, W0.y), pk16(W0.z, W0.w)); \
        *(uint2*)&Bsh[NB][lbk1][lbn1] = make_uint2(pk16(W1.x, W1.y), pk16(W1.z, W1.w)); \
    } while (0)

#define GEMM_BODY(T, SW0, SW1, LW0, LW1) do { \
        if ((T) + 1 < ntiles) cp_wait<1>(); else cp_wait<0>(); \
        __syncthreads(); \
        if ((T) + 2 < ntiles) { \
            cp16(&As[swr][lar][lacH], Aread + (((T) + 2) << 4)); \
            cp_commit(); \
        } \
        if ((T) + 1 < ntiles) { STS_B(((T) + 1) & 1, SW0, SW1); } \
        if ((T) + 2 < ntiles) { LDG_B(LW0, LW1, (T) + 2); } \
        /* B fragments: 2x ldmatrix.x4.trans */ \
        uint32_t bfr[8]; \
        { \
            const uint32_t bAddr = bsBase + \
                ((uint32_t)((((T) & 1) * 16) + ldrow) * BSTRH + wn + ldcol) * 2u; \
            ldsm4t(bfr[0], bfr[1], bfr[2], bfr[3], bAddr); \
            ldsm4t(bfr[4], bfr[5], bfr[6], bfr[7], bAddr + 32u); \
        } \
        _Pragma("unroll") \
        for (int tt = 0; tt < 4; ++tt) { \
            const int rr = wm + tt * 16; \
            uint32_t a0, a1, a2, a3; \
            const uint32_t aAddr = asBase + \
                ((uint32_t)(scur * 128 + rr + ldrow) * ASTRH + ldcol) * 2u; \
            ldsm4(a0, a1, a2, a3, aAddr); \
            _Pragma("unroll") \
            for (int u = 0; u < 4; ++u) \
                mma_f16(acc[tt][u][0], acc[tt][u][1], acc[tt][u][2], acc[tt][u][3], \
                        a0, a1, a2, a3, bfr[u*2], bfr[u*2 + 1]); \
        } \
        scur = (scur == 2) ? 0 : scur + 1; \
        swr  = (swr  == 2) ? 0 : swr  + 1; \
    } while (0)

    // ---- prologue: A tiles 0,1 in flight; B tile 0 staged, tile 1 in regs ----
    int scur = 0, swr = 2;   // swr tracks (t+2)%3
    float4 wA0, wA1, wB0, wB1;
    cp16(&As[0][lar][lacH], Aread);
    cp_commit();
    cp16(&As[1][lar][lacH], Aread + 16);
    cp_commit();
    LDG_B(wA0, wA1, 0);
    STS_B(0, wA0, wA1);
    if (ntiles > 1) { LDG_B(wA0, wA1, 1); }

    for (int t = 0; t < ntiles; t += 2) {
        GEMM_BODY(t,     wA0, wA1, wB0, wB1);
        GEMM_BODY(t + 1, wB0, wB1, wA0, wA1);
    }

#undef GEMM_BODY
#undef STS_B
#undef LDG_B

    // ---- epilogue ----
    #pragma unroll
    for (int t = 0; t < 4; ++t) {
        #pragma unroll
        for (int u = 0; u < 4; ++u) {
            const int m = m0 + wm + t*16 + gid;
            const int n = n0 + wn + u*8 + tig*2;
            float v0 = acc[t][u][0], v1 = acc[t][u][1];
            float v2 = acc[t][u][2], v3 = acc[t][u][3];
            if (MODE >= 1) {
                float b0 = bias[n], b1 = bias[n+1];
                v0 += b0; v1 += b1; v2 += b0; v3 += b1;
            }
            if (MODE == 1) {
                v0 = fmaxf(v0, 0.f); v1 = fmaxf(v1, 0.f);
                v2 = fmaxf(v2, 0.f); v3 = fmaxf(v3, 0.f);
            }
            if (MODE <= 1) {
                __half* Ch = (__half*)Cv;
                *(__half2*)(Ch + (size_t)m * N + n)     = __floats2half2_rn(v0, v1);
                *(__half2*)(Ch + (size_t)(m+8) * N + n) = __floats2half2_rn(v2, v3);
            } else {
                float* Cf = (float*)Cv;
                const float2 r0 = *(const float2*)(res + (size_t)m * N + n);
                const float2 r1 = *(const float2*)(res + (size_t)(m+8) * N + n);
                *(float2*)(Cf + (size_t)m * N + n)     = make_float2(v0 + r0.x, v1 + r0.y);
                *(float2*)(Cf + (size_t)(m+8) * N + n) = make_float2(v2 + r1.x, v3 + r1.y);
            }
        }
    }
}

// ---------------- Flash attention (fp16 mma): 128 thr, 64-row CTA, 32-key chunks ----------------
__global__ __launch_bounds__(128) void flash_kernel(const float* __restrict__ embds,
                                                    float* __restrict__ out)
{
    __shared__ __align__(16) __half Qh[64][72];
    __shared__ __align__(16) __half Kh[32][72];
    __shared__ __align__(16) __half Vh[32][72];
    __shared__ __align__(16) __half Ph[64][40];

    const int it = gridDim.x - 1 - blockIdx.x;   // heavy tiles first
    const int bh = blockIdx.y;
    const int b = bh >> 4, h = bh & 15;
    const int tid = threadIdx.x, warp = tid >> 5, lane = tid & 31;
    const int gid = lane >> 2, tig = lane & 3;
    const int i0 = it * 64;
    const int wr = i0 + warp * 16;

    const int ldrow = (lane & 7) + ((lane >> 3) & 1) * 8;
    const int ldcol = (lane >> 4) * 8;
    const uint32_t qBase = (uint32_t)__cvta_generic_to_shared(&Qh[0][0]);
    const uint32_t kBase = (uint32_t)__cvta_generic_to_shared(&Kh[0][0]);
    const uint32_t vBase = (uint32_t)__cvta_generic_to_shared(&Vh[0][0]);
    const uint32_t pBase = (uint32_t)__cvta_generic_to_shared(&Ph[0][0]);

    // stage Q tile: 64 rows x 64 halves (cp.async)
    #pragma unroll
    for (int l = 0; l < 4; ++l) {
        int idx = l * 128 + tid;
        int r = idx >> 3, c8 = (idx & 7) * 8;
        cp16(&Qh[r][c8], g_qh + (((size_t)(b*T_ + i0 + r))*H_ + h)*HS_ + c8);
    }
    cp_commit();

    float oacc[8][4];
    #pragma unroll
    for (int u = 0; u < 8; ++u)
        #pragma unroll
        for (int c = 0; c < 4; ++c) oacc[u][c] = 0.f;
    float mrow[2] = {-1e30f, -1e30f};
    float lrow[2] = {0.f, 0.f};

    const int njc = 2*it + 2;
    for (int jc = 0; jc < njc; ++jc) {
        const int j0 = jc * 32;
        __syncthreads();   // previous K/V consumed (and Qh staging ordered at jc=0)
        #pragma unroll
        for (int l = 0; l < 2; ++l) {
            int idx = l * 128 + tid;
            int r = idx >> 3, c8 = (idx & 7) * 8;
            const size_t grow = (((size_t)(b*T_ + j0 + r))*H_ + h)*HS_ + c8;
            cp16(&Kh[r][c8], g_kh + grow);
            cp16(&Vh[r][c8], g_vh + grow);
        }
        cp_commit();
        cp_wait<0>();
        __syncthreads();

        if (j0 <= wr + 15) {
            // --- S = Q K^T (16 rows x 32 keys), fp16 k16 mma ---
            float sacc[4][4];
            #pragma unroll
            for (int u = 0; u < 4; ++u)
                #pragma unroll
                for (int c = 0; c < 4; ++c) sacc[u][c] = 0.f;
            #pragma unroll
            for (int kc = 0; kc < 4; ++kc) {
                uint32_t a0, a1, a2, a3;
                ldsm4(a0, a1, a2, a3,
                      qBase + ((uint32_t)(warp*16 + ldrow) * 72 + kc*16 + ldcol) * 2u);
                uint32_t r0, r1, r2, r3, s0, s1, s2, s3;
                ldsm4(r0, r1, r2, r3,
                      kBase + ((uint32_t)(ldrow) * 72 + kc*16 + ldcol) * 2u);
                ldsm4(s0, s1, s2, s3,
                      kBase + ((uint32_t)(16 + ldrow) * 72 + kc*16 + ldcol) * 2u);
                mma_f16(sacc[0][0], sacc[0][1], sacc[0][2], sacc[0][3], a0,a1,a2,a3, r0, r2);
                mma_f16(sacc[1][0], sacc[1][1], sacc[1][2], sacc[1][3], a0,a1,a2,a3, r1, r3);
                mma_f16(sacc[2][0], sacc[2][1], sacc[2][2], sacc[2][3], a0,a1,a2,a3, s0, s2);
                mma_f16(sacc[3][0], sacc[3][1], sacc[3][2], sacc[3][3], a0,a1,a2,a3, s1, s3);
            }

            // --- online softmax on 32-col chunk, P -> fp16 smem ---
            const bool maskneed = (j0 + 31 > wr);
            #pragma unroll
            for (int rh = 0; rh < 2; ++rh) {
                const int row = wr + gid + rh*8;
                float tmax = -1e30f;
                #pragma unroll
                for (int u = 0; u < 4; ++u) {
                    float x0 = sacc[u][rh*2    ] * 0.03125f;
                    float x1 = sacc[u][rh*2 + 1] * 0.03125f;
                    if (maskneed) {
                        const int c = j0 + u*8 + tig*2;
                        if (c     > row) x0 = -1e30f;
                        if (c + 1 > row) x1 = -1e30f;
                    }
                    sacc[u][rh*2    ] = x0;
                    sacc[u][rh*2 + 1] = x1;
                    tmax = fmaxf(tmax, fmaxf(x0, x1));
                }
                tmax = fmaxf(tmax, __shfl_xor_sync(0xffffffffu, tmax, 1));
                tmax = fmaxf(tmax, __shfl_xor_sync(0xffffffffu, tmax, 2));
                const float mnew = fmaxf(mrow[rh], tmax);
                const float corr = __expf(mrow[rh] - mnew);
                float rsum = 0.f;
                #pragma unroll
                for (int u = 0; u < 4; ++u) {
                    float p0 = __expf(sacc[u][rh*2    ] - mnew);
                    float p1 = __expf(sacc[u][rh*2 + 1] - mnew);
                    rsum += p0 + p1;
                    *(uint32_t*)(&Ph[warp*16 + gid + rh*8][u*8 + tig*2]) = pk16(p0, p1);
                }
                #pragma unroll
                for (int uu = 0; uu < 8; ++uu) {
                    oacc[uu][rh*2    ] *= corr;
                    oacc[uu][rh*2 + 1] *= corr;
                }
                rsum += __shfl_xor_sync(0xffffffffu, rsum, 1);
                rsum += __shfl_xor_sync(0xffffffffu, rsum, 2);
                lrow[rh] = lrow[rh] * corr + rsum;
                mrow[rh] = mnew;
            }
            __syncwarp();

            // --- O += P(16x32) V(32x64), fp16 k16 mma; V via ldsm.trans ---
            #pragma unroll
            for (int kc = 0; kc < 2; ++kc) {
                uint32_t a0, a1, a2, a3;
                ldsm4(a0, a1, a2, a3,
                      pBase + ((uint32_t)(warp*16 + ldrow) * 40 + kc*16 + ldcol) * 2u);
                #pragma unroll
                for (int nq = 0; nq < 4; ++nq) {
                    uint32_t r0, r1, r2, r3;
                    ldsm4t(r0, r1, r2, r3,
                           vBase + ((uint32_t)(kc*16 + ldrow) * 72 + nq*16 + ldcol) * 2u);
                    mma_f16(oacc[nq*2  ][0], oacc[nq*2  ][1], oacc[nq*2  ][2], oacc[nq*2  ][3],
                            a0, a1, a2, a3, r0, r1);
                    mma_f16(oacc[nq*2+1][0], oacc[nq*2+1][1], oacc[nq*2+1][2], oacc[nq*2+1][3],
                            a0, a1, a2, a3, r2, r3);
                }
            }
        }
    }

    // --- epilogue: /rowsum + residual, head-concat layout ---
    #pragma unroll
    for (int rh = 0; rh < 2; ++rh) {
        const int t = wr + gid + rh*8;
        const float inv = 1.0f / lrow[rh];
        #pragma unroll
        for (int u = 0; u < 8; ++u) {
            const int d = h * HS_ + u*8 + tig*2;
            const size_t o = ((size_t)(b*T_ + t))*D_ + d;
            const float2 e = *(const float2*)(embds + o);
            *(float2*)(out + o) = make_float2(e.x + oacc[u][rh*2    ]*inv,
                                              e.y + oacc[u][rh*2 + 1]*inv);
        }
    }
}

// ---------------- Launcher ----------------
extern "C" void kernel_launch(void* const* d_in, const int* in_sizes, int n_in,
                              void* d_out, int out_size)
{
    const float* embds = (const float*)d_in[0];
    const float* Wq    = (const float*)d_in[1];
    const float* Wk    = (const float*)d_in[2];
    const float* Wv    = (const float*)d_in[3];
    const float* ln1g  = (const float*)d_in[4];
    const float* ln1b  = (const float*)d_in[5];
    const float* ln2g  = (const float*)d_in[6];
    const float* ln2b  = (const float*)d_in[7];
    const float* W1    = (const float*)d_in[8];
    const float* b1    = (const float*)d_in[9];
    const float* W2    = (const float*)d_in[10];
    const float* b2    = (const float*)d_in[11];
    float* out = (float*)d_out;

    __half *xh, *fh, *qh, *kh, *vh;
    float *res1;
    cudaGetSymbolAddress((void**)&xh,   g_xh);
    cudaGetSymbolAddress((void**)&fh,   g_fh);
    cudaGetSymbolAddress((void**)&qh,   g_qh);
    cudaGetSymbolAddress((void**)&kh,   g_kh);
    cudaGetSymbolAddress((void**)&vh,   g_vh);
    cudaGetSymbolAddress((void**)&res1, g_res1);

    // 1. LN1 -> fp16
    ln_kernel<<<BT_, 256>>>(embds, ln1g, ln1b, xh);

    // 2. Fused QKV via gridDim.z -> qh, kh, vh [B,T,H,HS] fp16
    tgemm_kernel<0><<<dim3(D_/128, BT_/128, 3), 256>>>(
        xh, Wq, Wk, Wv, nullptr, nullptr, qh, kh, vh, BT_, D_, D_);

    // 3. Flash attention + head-concat + residual -> res1
    flash_kernel<<<dim3(T_/64, BH_), 128>>>(embds, res1);

    // 4. LN2 -> fp16
    ln_kernel<<<BT_, 256>>>(res1, ln2g, ln2b, xh);

    // 5. FFN1: relu(y @ W1 + b1) -> fp16 fh
    tgemm_kernel<1><<<dim3(4*D_/128, BT_/128), 256>>>(
        xh, W1, nullptr, nullptr, b1, nullptr, fh, nullptr, nullptr, BT_, 4*D_, D_);

    // 6. FFN2: fh @ W2 + b2 + res1 -> out (fp32)
    tgemm_kernel<2><<<dim3(D_/128, BT_/128), 256>>>(
        fh, W2, nullptr, nullptr, b2, res1, out, nullptr, nullptr, BT_, D_, 4*D_);
}

// round 14
// speedup vs baseline: 2.0568x; 1.1553x over previous
#include <cuda_runtime.h>
#include <cuda_fp16.h>
#include <math.h>
#include <stdint.h>

// ---------------- Problem dims ----------------
#define B_  2
#define T_  2048
#define D_  1024
#define H_  16
#define HS_ 64
#define BT_ (B_*T_)      // 4096
#define BH_ (B_*H_)      // 32
#define EPS_ 1e-5f

// ---------------- Scratch (static device memory; no allocations) ----------------
__device__ __align__(16) __half g_xh [BT_*D_];            // LN out, fp16
__device__ __align__(16) __half g_fh [(size_t)BT_*4*D_];  // FFN1 out, fp16
__device__ __align__(16) __half g_qh [BT_*D_];            // [B,T,H,HS] fp16
__device__ __align__(16) __half g_kh [BT_*D_];
__device__ __align__(16) __half g_vh [BT_*D_];
__device__ __align__(16) float  g_res1[BT_*D_];

// ---------------- Helpers ----------------
__device__ __forceinline__ uint32_t pk16(float lo, float hi) {
    uint32_t d;
    asm("cvt.rn.f16x2.f32 %0, %1, %2;" : "=r"(d) : "f"(hi), "f"(lo));
    return d;
}
__device__ __forceinline__ void mma_f16(float& c0, float& c1, float& c2, float& c3,
                                        uint32_t a0, uint32_t a1, uint32_t a2, uint32_t a3,
                                        uint32_t b0, uint32_t b1)
{
    asm volatile("mma.sync.aligned.m16n8k16.row.col.f32.f16.f16.f32 "
                 "{%0,%1,%2,%3}, {%4,%5,%6,%7}, {%8,%9}, {%0,%1,%2,%3};"
                 : "+f"(c0), "+f"(c1), "+f"(c2), "+f"(c3)
                 : "r"(a0), "r"(a1), "r"(a2), "r"(a3), "r"(b0), "r"(b1));
}
__device__ __forceinline__ void cp16(void* s, const void* g) {
    uint32_t sa = (uint32_t)__cvta_generic_to_shared(s);
    asm volatile("cp.async.cg.shared.global [%0], [%1], 16;" :: "r"(sa), "l"(g));
}
__device__ __forceinline__ void cp_commit() { asm volatile("cp.async.commit_group;" ::: "memory"); }
template<int N>
__device__ __forceinline__ void cp_wait() { asm volatile("cp.async.wait_group %0;" :: "n"(N) : "memory"); }
__device__ __forceinline__ void ldsm4(uint32_t& a0, uint32_t& a1, uint32_t& a2, uint32_t& a3,
                                      uint32_t addr)
{
    asm volatile("ldmatrix.sync.aligned.m8n8.x4.shared.b16 {%0,%1,%2,%3}, [%4];"
                 : "=r"(a0), "=r"(a1), "=r"(a2), "=r"(a3) : "r"(addr));
}
__device__ __forceinline__ void ldsm4t(uint32_t& a0, uint32_t& a1, uint32_t& a2, uint32_t& a3,
                                       uint32_t addr)
{
    asm volatile("ldmatrix.sync.aligned.m8n8.x4.trans.shared.b16 {%0,%1,%2,%3}, [%4];"
                 : "=r"(a0), "=r"(a1), "=r"(a2), "=r"(a3) : "r"(addr));
}

// ---------------- LayerNorm (fp16 output) ----------------
__global__ __launch_bounds__(256) void ln_kernel(const float* __restrict__ x,
                                                 const float* __restrict__ gam,
                                                 const float* __restrict__ bet,
                                                 __half* __restrict__ y)
{
    const int row = blockIdx.x;
    const int tid = threadIdx.x;
    const float4 v = *(const float4*)(x + (size_t)row*D_ + tid*4);
    float s  = v.x + v.y + v.z + v.w;
    float s2 = v.x*v.x + v.y*v.y + v.z*v.z + v.w*v.w;
    __shared__ float shs[8], shs2[8], stat[2];
    #pragma unroll
    for (int o = 16; o; o >>= 1) {
        s  += __shfl_xor_sync(0xffffffffu, s,  o);
        s2 += __shfl_xor_sync(0xffffffffu, s2, o);
    }
    if ((tid & 31) == 0) { shs[tid >> 5] = s; shs2[tid >> 5] = s2; }
    __syncthreads();
    if (tid == 0) {
        float ts = 0.f, ts2 = 0.f;
        #pragma unroll
        for (int w = 0; w < 8; ++w) { ts += shs[w]; ts2 += shs2[w]; }
        float mean = ts * (1.0f / D_);
        float var  = ts2 * (1.0f / D_) - mean * mean;
        stat[0] = mean; stat[1] = rsqrtf(var + EPS_);
    }
    __syncthreads();
    const float mean = stat[0], rstd = stat[1];
    const float4 g4 = *(const float4*)(gam + tid*4);
    const float4 b4 = *(const float4*)(bet + tid*4);
    __half2 ha = __floats2half2_rn((v.x - mean) * rstd * g4.x + b4.x,
                                   (v.y - mean) * rstd * g4.y + b4.y);
    __half2 hb = __floats2half2_rn((v.z - mean) * rstd * g4.z + b4.z,
                                   (v.w - mean) * rstd * g4.w + b4.w);
    __half2* yp = (__half2*)(y + (size_t)row*D_ + tid*4);
    yp[0] = ha; yp[1] = hb;
}

// ---------------- fp16 GEMM: 128x128 tile, BK=32, 3-stage A / 2-stage B ----------------
// MODE 0: QKV (z-select; MAPB layout, no bias) -> fp16 out
// MODE 1: FFN1 (bias + relu)                   -> fp16 out
// MODE 2: FFN2 (bias + residual)               -> fp32 out
#define ASTRH 40
#define BSTRH 136

template<int MODE>
__global__ __launch_bounds__(256) void tgemm_kernel(
    const __half* __restrict__ A,
    const float* __restrict__ B0, const float* __restrict__ B1, const float* __restrict__ B2,
    const float* __restrict__ bias, const float* __restrict__ res,
    void* __restrict__ C0, void* __restrict__ C1, void* __restrict__ C2,
    int M, int N, int K)
{
    __shared__ __align__(16) __half As[3][128][ASTRH];    // 30720 B
    __shared__ __align__(16) __half Bsh[2][32][BSTRH];    // 17408 B

    const float* Bm;
    void* Cv;
    if (MODE == 0) {
        Bm = (blockIdx.z == 0) ? B0 : (blockIdx.z == 1 ? B1 : B2);
        Cv = (blockIdx.z == 0) ? C0 : (blockIdx.z == 1 ? C1 : C2);
    } else {
        Bm = B0;
        Cv = C0;
    }

    const int tid  = threadIdx.x;
    const int m0 = blockIdx.y * 128, n0 = blockIdx.x * 128;
    const int warp = tid >> 5, lane = tid & 31;
    const int gid = lane >> 2, tig = lane & 3;
    const int wm = (warp >> 2) * 64;   // 0,64
    const int wn = (warp & 3) * 32;    // 0,32,64,96

    const int ldrow = (lane & 7) + ((lane >> 3) & 1) * 8;
    const int ldcol = (lane >> 4) * 8;
    const uint32_t asBase = (uint32_t)__cvta_generic_to_shared(&As[0][0][0]);
    const uint32_t bsBase = (uint32_t)__cvta_generic_to_shared(&Bsh[0][0][0]);

    // A fill: 2 x 16B per thread per 32-k tile (128 rows x 32 halves)
    const int lar = tid >> 2;             // 0..63
    const int lacH = (tid & 3) * 8;       // 0,8,16,24
    // B fill: 4 float4 per thread per tile (32 rows x 128 floats)
    const int lbk = tid >> 5;             // 0..7 (+8*l)
    const int lbn = (tid & 31) * 4;

    const __half* Aread = A + (size_t)(m0 + lar) * K + lacH;

    float acc[4][4][4];
    #pragma unroll
    for (int t = 0; t < 4; ++t)
        #pragma unroll
        for (int u = 0; u < 4; ++u)
            #pragma unroll
            for (int c = 0; c < 4; ++c) acc[t][u][c] = 0.f;

    const int ntiles = K >> 5;   // 32 or 128 (even)

#define CP_A(ST, TT) do { \
        cp16(&As[ST][lar     ][lacH], Aread + ((TT) << 5)); \
        cp16(&As[ST][lar + 64][lacH], Aread + (size_t)64 * K + ((TT) << 5)); \
        cp_commit(); \
    } while (0)

#define LDG_B(DST, TT) do { \
        _Pragma("unroll") \
        for (int l_ = 0; l_ < 4; ++l_) { \
            if (MODE == 0) { \
                int c_ = n0 + lbn; \
                DST[l_] = *(const float4*)(Bm + ((size_t)(c_ >> 6) * K + ((TT) << 5) + lbk + 8*l_) * HS_ + (c_ & 63)); \
            } else { \
                DST[l_] = *(const float4*)(Bm + (size_t)(((TT) << 5) + lbk + 8*l_) * N + n0 + lbn); \
            } \
        } \
    } while (0)

#define STS_B(NB, W) do { \
        _Pragma("unroll") \
        for (int l_ = 0; l_ < 4; ++l_) \
            *(uint2*)&Bsh[NB][lbk + 8*l_][lbn] = \
                make_uint2(pk16(W[l_].x, W[l_].y), pk16(W[l_].z, W[l_].w)); \
    } while (0)

#define GEMM_BODY(T, SW, LW) do { \
        if ((T) + 1 < ntiles) cp_wait<1>(); else cp_wait<0>(); \
        __syncthreads(); \
        if ((T) + 2 < ntiles) { CP_A(swr, (T) + 2); } \
        if ((T) + 1 < ntiles) { STS_B(((T) + 1) & 1, SW); } \
        if ((T) + 2 < ntiles) { LDG_B(LW, (T) + 2); } \
        _Pragma("unroll") \
        for (int kc = 0; kc < 2; ++kc) { \
            uint32_t bfr[8]; \
            const uint32_t bAddr = bsBase + \
                ((uint32_t)((((T) & 1) * 32) + kc*16 + ldrow) * BSTRH + wn + ldcol) * 2u; \
            ldsm4t(bfr[0], bfr[1], bfr[2], bfr[3], bAddr); \
            ldsm4t(bfr[4], bfr[5], bfr[6], bfr[7], bAddr + 32u); \
            _Pragma("unroll") \
            for (int tt = 0; tt < 4; ++tt) { \
                const int rr = wm + tt * 16; \
                uint32_t a0, a1, a2, a3; \
                const uint32_t aAddr = asBase + \
                    ((uint32_t)(scur * 128 + rr + ldrow) * ASTRH + kc*16 + ldcol) * 2u; \
                ldsm4(a0, a1, a2, a3, aAddr); \
                _Pragma("unroll") \
                for (int u = 0; u < 4; ++u) \
                    mma_f16(acc[tt][u][0], acc[tt][u][1], acc[tt][u][2], acc[tt][u][3], \
                            a0, a1, a2, a3, bfr[u*2], bfr[u*2 + 1]); \
            } \
        } \
        scur = (scur == 2) ? 0 : scur + 1; \
        swr  = (swr  == 2) ? 0 : swr  + 1; \
    } while (0)

    // ---- prologue: A tiles 0,1 in flight; B tile 0 staged, tile 1 in regs ----
    int scur = 0, swr = 2;
    float4 wA[4], wB[4];
    CP_A(0, 0);
    CP_A(1, 1);
    LDG_B(wA, 0);
    STS_B(0, wA);
    if (ntiles > 1) { LDG_B(wA, 1); }

    for (int t = 0; t < ntiles; t += 2) {
        GEMM_BODY(t,     wA, wB);
        GEMM_BODY(t + 1, wB, wA);
    }

#undef GEMM_BODY
#undef STS_B
#undef LDG_B
#undef CP_A

    // ---- epilogue ----
    #pragma unroll
    for (int t = 0; t < 4; ++t) {
        #pragma unroll
        for (int u = 0; u < 4; ++u) {
            const int m = m0 + wm + t*16 + gid;
            const int n = n0 + wn + u*8 + tig*2;
            float v0 = acc[t][u][0], v1 = acc[t][u][1];
            float v2 = acc[t][u][2], v3 = acc[t][u][3];
            if (MODE >= 1) {
                float b0 = bias[n], b1 = bias[n+1];
                v0 += b0; v1 += b1; v2 += b0; v3 += b1;
            }
            if (MODE == 1) {
                v0 = fmaxf(v0, 0.f); v1 = fmaxf(v1, 0.f);
                v2 = fmaxf(v2, 0.f); v3 = fmaxf(v3, 0.f);
            }
            if (MODE <= 1) {
                __half* Ch = (__half*)Cv;
                *(__half2*)(Ch + (size_t)m * N + n)     = __floats2half2_rn(v0, v1);
                *(__half2*)(Ch + (size_t)(m+8) * N + n) = __floats2half2_rn(v2, v3);
            } else {
                float* Cf = (float*)Cv;
                const float2 r0 = *(const float2*)(res + (size_t)m * N + n);
                const float2 r1 = *(const float2*)(res + (size_t)(m+8) * N + n);
                *(float2*)(Cf + (size_t)m * N + n)     = make_float2(v0 + r0.x, v1 + r0.y);
                *(float2*)(Cf + (size_t)(m+8) * N + n) = make_float2(v2 + r1.x, v3 + r1.y);
            }
        }
    }
}

// ---------------- Flash attention (fp16 mma, double-buffered K/V) ----------------
__global__ __launch_bounds__(128) void flash_kernel(const float* __restrict__ embds,
                                                    float* __restrict__ out)
{
    __shared__ __align__(16) __half Qh[64][72];
    __shared__ __align__(16) __half Kh[2][32][72];
    __shared__ __align__(16) __half Vh[2][32][72];
    __shared__ __align__(16) __half Ph[64][40];

    const int it = gridDim.x - 1 - blockIdx.x;   // heavy tiles first
    const int bh = blockIdx.y;
    const int b = bh >> 4, h = bh & 15;
    const int tid = threadIdx.x, warp = tid >> 5, lane = tid & 31;
    const int gid = lane >> 2, tig = lane & 3;
    const int i0 = it * 64;
    const int wr = i0 + warp * 16;

    const int ldrow = (lane & 7) + ((lane >> 3) & 1) * 8;
    const int ldcol = (lane >> 4) * 8;
    const uint32_t qBase = (uint32_t)__cvta_generic_to_shared(&Qh[0][0]);
    const uint32_t kBase = (uint32_t)__cvta_generic_to_shared(&Kh[0][0][0]);
    const uint32_t vBase = (uint32_t)__cvta_generic_to_shared(&Vh[0][0][0]);
    const uint32_t pBase = (uint32_t)__cvta_generic_to_shared(&Ph[0][0]);

    // K/V chunk load coords: 2 x 16B per thread per chunk (32 rows x 64 halves)
    const int kvr = tid >> 3;            // 0..15 (+16 on second)
    const int kvc = (tid & 7) * 8;

    // stage Q tile (group 0): 64 rows x 64 halves
    #pragma unroll
    for (int l = 0; l < 4; ++l) {
        int idx = l * 128 + tid;
        int r = idx >> 3, c8 = (idx & 7) * 8;
        cp16(&Qh[r][c8], g_qh + (((size_t)(b*T_ + i0 + r))*H_ + h)*HS_ + c8);
    }
    cp_commit();

#define LOAD_KV(JC, BUF) do { \
        const size_t rowb = (size_t)(b*T_ + (JC)*32); \
        cp16(&Kh[BUF][kvr     ][kvc], g_kh + ((rowb + kvr     )*H_ + h)*HS_ + kvc); \
        cp16(&Kh[BUF][kvr + 16][kvc], g_kh + ((rowb + kvr + 16)*H_ + h)*HS_ + kvc); \
        cp16(&Vh[BUF][kvr     ][kvc], g_vh + ((rowb + kvr     )*H_ + h)*HS_ + kvc); \
        cp16(&Vh[BUF][kvr + 16][kvc], g_vh + ((rowb + kvr + 16)*H_ + h)*HS_ + kvc); \
        cp_commit(); \
    } while (0)

    float oacc[8][4];
    #pragma unroll
    for (int u = 0; u < 8; ++u)
        #pragma unroll
        for (int c = 0; c < 4; ++c) oacc[u][c] = 0.f;
    float mrow[2] = {-1e30f, -1e30f};
    float lrow[2] = {0.f, 0.f};

    const int njc = 2*it + 2;
    LOAD_KV(0, 0);   // group 1

    for (int jc = 0; jc < njc; ++jc) {
        const int j0 = jc * 32;
        const int buf = jc & 1;
        if (jc + 1 < njc) { LOAD_KV(jc + 1, buf ^ 1); cp_wait<1>(); }
        else              { cp_wait<0>(); }
        __syncthreads();

        if (j0 <= wr + 15) {
            // --- S = Q K^T (16 rows x 32 keys) ---
            float sacc[4][4];
            #pragma unroll
            for (int u = 0; u < 4; ++u)
                #pragma unroll
                for (int c = 0; c < 4; ++c) sacc[u][c] = 0.f;
            #pragma unroll
            for (int kc = 0; kc < 4; ++kc) {
                uint32_t a0, a1, a2, a3;
                ldsm4(a0, a1, a2, a3,
                      qBase + ((uint32_t)(warp*16 + ldrow) * 72 + kc*16 + ldcol) * 2u);
                uint32_t r0, r1, r2, r3, s0, s1, s2, s3;
                ldsm4(r0, r1, r2, r3,
                      kBase + ((uint32_t)(buf*32 + ldrow) * 72 + kc*16 + ldcol) * 2u);
                ldsm4(s0, s1, s2, s3,
                      kBase + ((uint32_t)(buf*32 + 16 + ldrow) * 72 + kc*16 + ldcol) * 2u);
                mma_f16(sacc[0][0], sacc[0][1], sacc[0][2], sacc[0][3], a0,a1,a2,a3, r0, r2);
                mma_f16(sacc[1][0], sacc[1][1], sacc[1][2], sacc[1][3], a0,a1,a2,a3, r1, r3);
                mma_f16(sacc[2][0], sacc[2][1], sacc[2][2], sacc[2][3], a0,a1,a2,a3, s0, s2);
                mma_f16(sacc[3][0], sacc[3][1], sacc[3][2], sacc[3][3], a0,a1,a2,a3, s1, s3);
            }

            // --- online softmax, P -> fp16 smem ---
            const bool maskneed = (j0 + 31 > wr);
            #pragma unroll
            for (int rh = 0; rh < 2; ++rh) {
                const int row = wr + gid + rh*8;
                float tmax = -1e30f;
                #pragma unroll
                for (int u = 0; u < 4; ++u) {
                    float x0 = sacc[u][rh*2    ] * 0.03125f;
                    float x1 = sacc[u][rh*2 + 1] * 0.03125f;
                    if (maskneed) {
                        const int c = j0 + u*8 + tig*2;
                        if (c     > row) x0 = -1e30f;
                        if (c + 1 > row) x1 = -1e30f;
                    }
                    sacc[u][rh*2    ] = x0;
                    sacc[u][rh*2 + 1] = x1;
                    tmax = fmaxf(tmax, fmaxf(x0, x1));
                }
                tmax = fmaxf(tmax, __shfl_xor_sync(0xffffffffu, tmax, 1));
                tmax = fmaxf(tmax, __shfl_xor_sync(0xffffffffu, tmax, 2));
                const float mnew = fmaxf(mrow[rh], tmax);
                const float corr = __expf(mrow[rh] - mnew);
                float rsum = 0.f;
                #pragma unroll
                for (int u = 0; u < 4; ++u) {
                    float p0 = __expf(sacc[u][rh*2    ] - mnew);
                    float p1 = __expf(sacc[u][rh*2 + 1] - mnew);
                    rsum += p0 + p1;
                    *(uint32_t*)(&Ph[warp*16 + gid + rh*8][u*8 + tig*2]) = pk16(p0, p1);
                }
                #pragma unroll
                for (int uu = 0; uu < 8; ++uu) {
                    oacc[uu][rh*2    ] *= corr;
                    oacc[uu][rh*2 + 1] *= corr;
                }
                rsum += __shfl_xor_sync(0xffffffffu, rsum, 1);
                rsum += __shfl_xor_sync(0xffffffffu, rsum, 2);
                lrow[rh] = lrow[rh] * corr + rsum;
                mrow[rh] = mnew;
            }
            __syncwarp();

            // --- O += P V, V via ldsm.trans ---
            #pragma unroll
            for (int kc = 0; kc < 2; ++kc) {
                uint32_t a0, a1, a2, a3;
                ldsm4(a0, a1, a2, a3,
                      pBase + ((uint32_t)(warp*16 + ldrow) * 40 + kc*16 + ldcol) * 2u);
                #pragma unroll
                for (int nq = 0; nq < 4; ++nq) {
                    uint32_t r0, r1, r2, r3;
                    ldsm4t(r0, r1, r2, r3,
                           vBase + ((uint32_t)(buf*32 + kc*16 + ldrow) * 72 + nq*16 + ldcol) * 2u);
                    mma_f16(oacc[nq*2  ][0], oacc[nq*2  ][1], oacc[nq*2  ][2], oacc[nq*2  ][3],
                            a0, a1, a2, a3, r0, r1);
                    mma_f16(oacc[nq*2+1][0], oacc[nq*2+1][1], oacc[nq*2+1][2], oacc[nq*2+1][3],
                            a0, a1, a2, a3, r2, r3);
                }
            }
        }
        __syncthreads();   // compute done before buf is overwritten at jc+1's prefetch of jc+2
    }
#undef LOAD_KV

    // --- epilogue: /rowsum + residual, head-concat ---
    #pragma unroll
    for (int rh = 0; rh < 2; ++rh) {
        const int t = wr + gid + rh*8;
        const float inv = 1.0f / lrow[rh];
        #pragma unroll
        for (int u = 0; u < 8; ++u) {
            const int d = h * HS_ + u*8 + tig*2;
            const size_t o = ((size_t)(b*T_ + t))*D_ + d;
            const float2 e = *(const float2*)(embds + o);
            *(float2*)(out + o) = make_float2(e.x + oacc[u][rh*2    ]*inv,
                                              e.y + oacc[u][rh*2 + 1]*inv);
        }
    }
}

// ---------------- Launcher ----------------
extern "C" void kernel_launch(void* const* d_in, const int* in_sizes, int n_in,
                              void* d_out, int out_size)
{
    const float* embds = (const float*)d_in[0];
    const float* Wq    = (const float*)d_in[1];
    const float* Wk    = (const float*)d_in[2];
    const float* Wv    = (const float*)d_in[3];
    const float* ln1g  = (const float*)d_in[4];
    const float* ln1b  = (const float*)d_in[5];
    const float* ln2g  = (const float*)d_in[6];
    const float* ln2b  = (const float*)d_in[7];
    const float* W1    = (const float*)d_in[8];
    const float* b1    = (const float*)d_in[9];
    const float* W2    = (const float*)d_in[10];
    const float* b2    = (const float*)d_in[11];
    float* out = (float*)d_out;

    __half *xh, *fh, *qh, *kh, *vh;
    float *res1;
    cudaGetSymbolAddress((void**)&xh,   g_xh);
    cudaGetSymbolAddress((void**)&fh,   g_fh);
    cudaGetSymbolAddress((void**)&qh,   g_qh);
    cudaGetSymbolAddress((void**)&kh,   g_kh);
    cudaGetSymbolAddress((void**)&vh,   g_vh);
    cudaGetSymbolAddress((void**)&res1, g_res1);

    // 1. LN1 -> fp16
    ln_kernel<<<BT_, 256>>>(embds, ln1g, ln1b, xh);

    // 2. Fused QKV via gridDim.z -> qh, kh, vh [B,T,H,HS] fp16
    tgemm_kernel<0><<<dim3(D_/128, BT_/128, 3), 256>>>(
        xh, Wq, Wk, Wv, nullptr, nullptr, qh, kh, vh, BT_, D_, D_);

    // 3. Flash attention + head-concat + residual -> res1
    flash_kernel<<<dim3(T_/64, BH_), 128>>>(embds, res1);

    // 4. LN2 -> fp16
    ln_kernel<<<BT_, 256>>>(res1, ln2g, ln2b, xh);

    // 5. FFN1: relu(y @ W1 + b1) -> fp16 fh
    tgemm_kernel<1><<<dim3(4*D_/128, BT_/128), 256>>>(
        xh, W1, nullptr, nullptr, b1, nullptr, fh, nullptr, nullptr, BT_, 4*D_, D_);

    // 6. FFN2: fh @ W2 + b2 + res1 -> out (fp32)
    tgemm_kernel<2><<<dim3(D_/128, BT_/128), 256>>>(
        fh, W2, nullptr, nullptr, b2, res1, out, nullptr, nullptr, BT_, D_, 4*D_);
}